// round 2
// baseline (speedup 1.0000x reference)
#include <cuda_runtime.h>
#include <math.h>

#define N_   4096
#define SEQ_ 41
#define VEC_ 15
#define T_   8
#define EMB_ 32
#define LDIM_ 256
#define RED_ 64

// ---------------- scratch (device globals; no allocation) ----------------
__device__ float g_h[N_ * EMB_];
__device__ float g_emb[N_ * EMB_];
__device__ float g_sqn[N_];
__device__ float g_mu[EMB_];
__device__ float g_rstd[EMB_];
__device__ float g_psum[1024];
__device__ float g_pmin[1024];
__device__ float g_pmax[1024];
__device__ float g_dc[3];            // avg, mn, inv
__device__ float g_posvec[N_ * RED_];
__device__ float g_negvec[N_ * RED_];
__device__ float g_psn[N_];
__device__ float g_nsn[N_];
__device__ float g_sp[1024];
__device__ float g_sn[1024];

__device__ __forceinline__ float fast_tanh(float x) {
    // 1 - 2/(e^{2x}+1): two MUFU ops, ~1e-6 accurate, handles +-inf correctly
    float e = __expf(2.0f * x);
    return 1.0f - 2.0f / (e + 1.0f);
}

// ---------------- K1: gather + interp + h = tanh(flat@W1 + b1) ----------------
__global__ void k_gather_h(const float* __restrict__ A, const int* __restrict__ C,
                           const float* __restrict__ W1, const float* __restrict__ b1) {
    __shared__ float flat[120];
    int n = blockIdx.x;
    int t = threadIdx.x;
    int start = C[2 * n], end = C[2 * n + 1];
    int len = end - start + 1;
    if (t < 120) {
        int j = t / VEC_, v = t % VEC_;
        float scale = (float)len / (float)T_;
        float src = fmaxf(scale * ((float)j + 0.5f) - 0.5f, 0.0f);
        int i0 = min((int)floorf(src), len - 1);
        int i1 = min(i0 + 1, len - 1);
        float w = src - (float)i0;
        const float* Ar = A + (size_t)n * SEQ_ * VEC_;
        float g0 = Ar[(start + i0) * VEC_ + v];
        float g1 = Ar[(start + i1) * VEC_ + v];
        flat[t] = (1.0f - w) * g0 + w * g1;
    }
    __syncthreads();
    if (t < 32) {
        float acc = b1[t];
#pragma unroll
        for (int k = 0; k < 120; k++) acc += flat[k] * W1[k * 32 + t];
        g_h[n * 32 + t] = tanhf(acc);
    }
}

// ---------------- K2: batchnorm stats over N ----------------
__global__ void k_bnstats() {
    __shared__ float ssum[32][33];
    __shared__ float ssq[32][33];
    int c = threadIdx.x & 31, g = threadIdx.x >> 5;  // 32 groups x 32 cols
    float s = 0.f, q = 0.f;
    for (int n = g; n < N_; n += 32) {
        float v = g_h[n * 32 + c];
        s += v; q += v * v;
    }
    ssum[g][c] = s; ssq[g][c] = q;
    __syncthreads();
    if (threadIdx.x < 32) {
        float S = 0.f, Q = 0.f;
        for (int gg = 0; gg < 32; gg++) { S += ssum[gg][threadIdx.x]; Q += ssq[gg][threadIdx.x]; }
        float mu = S / (float)N_;
        float var = Q / (float)N_ - mu * mu;
        g_mu[threadIdx.x] = mu;
        g_rstd[threadIdx.x] = rsqrtf(var + 1e-5f);
    }
}

// ---------------- K3: emb + row sq-norms ----------------
__global__ void k_emb(const float* __restrict__ gamma, const float* __restrict__ beta) {
    int idx = blockIdx.x * 256 + threadIdx.x;   // 512 blocks
    int c = idx & 31;
    float e = gamma[c] * (g_h[idx] - g_mu[c]) * g_rstd[c] + beta[c];
    g_emb[idx] = e;
    float sq = e * e;
#pragma unroll
    for (int o = 16; o; o >>= 1) sq += __shfl_xor_sync(0xffffffffu, sq, o);
    if (c == 0) g_sqn[idx >> 5] = sq;
}

// ---------------- D tiles: 128x128 per block, k=32 ----------------
__device__ __forceinline__ void d_tile_gemm(int bi, int bj, int t,
                                            float sI[128][33], float sJ[128][33],
                                            float snI[128], float snJ[128],
                                            float acc[8][8]) {
    for (int i = t; i < 128 * 32; i += 256) {
        int r = i >> 5, k = i & 31;
        sI[r][k] = g_emb[(bi * 128 + r) * 32 + k];
        sJ[r][k] = g_emb[(bj * 128 + r) * 32 + k];
    }
    if (t < 128) snI[t] = g_sqn[bi * 128 + t];
    else snJ[t - 128] = g_sqn[bj * 128 + (t - 128)];
    __syncthreads();
    int tx = t & 15, ty = t >> 4;
#pragma unroll
    for (int k = 0; k < 32; k++) {
        float a[8], b[8];
#pragma unroll
        for (int r = 0; r < 8; r++) a[r] = sI[ty + 16 * r][k];
#pragma unroll
        for (int c = 0; c < 8; c++) b[c] = sJ[tx + 16 * c][k];
#pragma unroll
        for (int r = 0; r < 8; r++)
#pragma unroll
            for (int c = 0; c < 8; c++) acc[r][c] += a[r] * b[c];
    }
}

__global__ void k_dstats(const float* __restrict__ sigma_p) {
    __shared__ float sI[128][33], sJ[128][33];
    __shared__ float snI[128], snJ[128];
    __shared__ float rs[256], rmn[256], rmx[256];
    int bi = blockIdx.y, bj = blockIdx.x, t = threadIdx.x;
    float acc[8][8];
#pragma unroll
    for (int r = 0; r < 8; r++)
#pragma unroll
        for (int c = 0; c < 8; c++) acc[r][c] = 0.f;
    d_tile_gemm(bi, bj, t, sI, sJ, snI, snJ, acc);
    float inv2s;
    { float sg = sigma_p[0]; inv2s = 0.5f / (sg * sg); }
    int tx = t & 15, ty = t >> 4;
    float lsum = 0.f, lmin = 3.4e38f, lmax = -3.4e38f;
#pragma unroll
    for (int r = 0; r < 8; r++) {
        int gi = bi * 128 + ty + 16 * r;
#pragma unroll
        for (int c = 0; c < 8; c++) {
            int gj = bj * 128 + tx + 16 * c;
            float sq = snI[ty + 16 * r] + snJ[tx + 16 * c] - 2.0f * acc[r][c];
            sq = fmaxf(sq, 0.0f);
            float d = (sq > 0.0f) ? sqrtf(sq) : 0.0f;
            float val = __expf(-d * inv2s);
            if (gi != gj) { lsum += val; lmin = fminf(lmin, val); lmax = fmaxf(lmax, val); }
        }
    }
    rs[t] = lsum; rmn[t] = lmin; rmx[t] = lmax;
    __syncthreads();
    for (int o = 128; o; o >>= 1) {
        if (t < o) {
            rs[t] += rs[t + o];
            rmn[t] = fminf(rmn[t], rmn[t + o]);
            rmx[t] = fmaxf(rmx[t], rmx[t + o]);
        }
        __syncthreads();
    }
    if (t == 0) {
        int bid = bi * 32 + bj;
        g_psum[bid] = rs[0]; g_pmin[bid] = rmn[0]; g_pmax[bid] = rmx[0];
    }
}

__global__ void k_dconsts() {
    __shared__ float rs[1024], rmn[1024], rmx[1024];
    int t = threadIdx.x;
    rs[t] = g_psum[t]; rmn[t] = g_pmin[t]; rmx[t] = g_pmax[t];
    __syncthreads();
    for (int o = 512; o; o >>= 1) {
        if (t < o) {
            rs[t] += rs[t + o];
            rmn[t] = fminf(rmn[t], rmn[t + o]);
            rmx[t] = fmaxf(rmx[t], rmx[t + o]);
        }
        __syncthreads();
    }
    if (t == 0) {
        float avg = rs[0] / ((float)N_ * (float)(N_ - 1));
        float mn = (rmn[0] < avg) ? 0.0f : rmn[0];
        float mx = rmx[0];
        if (mx == mn) mx = mn + 1.0f;
        g_dc[0] = avg; g_dc[1] = mn; g_dc[2] = 1.0f / (mx - mn);
    }
}

__global__ void k_dwrite(const float* __restrict__ sigma_p, float* __restrict__ D) {
    __shared__ float sI[128][33], sJ[128][33];
    __shared__ float snI[128], snJ[128];
    int bi = blockIdx.y, bj = blockIdx.x, t = threadIdx.x;
    float acc[8][8];
#pragma unroll
    for (int r = 0; r < 8; r++)
#pragma unroll
        for (int c = 0; c < 8; c++) acc[r][c] = 0.f;
    d_tile_gemm(bi, bj, t, sI, sJ, snI, snJ, acc);
    float inv2s;
    { float sg = sigma_p[0]; inv2s = 0.5f / (sg * sg); }
    float avg = g_dc[0], mn = g_dc[1], inv = g_dc[2];
    int tx = t & 15, ty = t >> 4;
#pragma unroll
    for (int r = 0; r < 8; r++) {
        int gi = bi * 128 + ty + 16 * r;
#pragma unroll
        for (int c = 0; c < 8; c++) {
            int gj = bj * 128 + tx + 16 * c;
            float sq = snI[ty + 16 * r] + snJ[tx + 16 * c] - 2.0f * acc[r][c];
            sq = fmaxf(sq, 0.0f);
            float d = (sq > 0.0f) ? sqrtf(sq) : 0.0f;
            float val = __expf(-d * inv2s);
            float out;
            if (gi == gj) out = 1.0f;
            else {
                float dt = (val < avg) ? 0.0f : val;
                out = (dt - mn) * inv;
            }
            D[(size_t)gi * N_ + gj] = out;
        }
    }
}

// ---------------- K7: fused projections  ----------------
// smem layout (floats):
//   sm_w   [128*192]       = 24576   (W chunks; later reused for W2s [64*128])
//   sm_l   [44*257]        = 11308   (l rows, padded; rows 41..43 zero)
//   sm_h   [44*132]        = 5808    (Hp | Hq, stride 132)
//   sm_red [11*192]        = 2112
//   sm_mp  [44], sm_mn[44], sm_ws[8]
#define PB 288
#define SMW 24576
#define SML 11308
#define SMH 5808
#define SMR 2112
#define LSTR 257
#define HSTR 132

__global__ void k_proj(const float* __restrict__ L, const float* __restrict__ Pw,
                       const float* __restrict__ Nw, const int* __restrict__ C,
                       const float* __restrict__ Wp1, const float* __restrict__ bp1,
                       const float* __restrict__ Wp2, const float* __restrict__ bp2,
                       const float* __restrict__ Wq1, const float* __restrict__ bq1,
                       const float* __restrict__ Wq2, const float* __restrict__ bq2,
                       const float* __restrict__ Wa, const float* __restrict__ ba,
                       float* __restrict__ out_ff) {
    extern __shared__ float sm[];
    float* sm_w = sm;
    float* sm_l = sm + SMW;
    float* sm_h = sm_l + SML;
    float* sm_red = sm_h + SMH;
    float* sm_mp = sm_red + SMR;
    float* sm_mn = sm_mp + 44;
    float* sm_ws = sm_mn + 44;

    int n = blockIdx.x;
    int t = threadIdx.x;

    // load l (pad rows zero)
    for (int i = t; i < 44 * 256; i += PB) {
        int s = i >> 8, k = i & 255;
        sm_l[s * LSTR + k] = (s < SEQ_) ? L[(size_t)n * SEQ_ * LDIM_ + i] : 0.0f;
    }
    if (t < 44) {
        float mp = 0.f, mq = 0.f;
        if (t < SEQ_) {
            int start = C[2 * n], end = C[2 * n + 1];
            bool in = (t >= start && t <= end);
            float pw = Pw[n * SEQ_ + t], nw = Nw[n * SEQ_ + t];
            mp = in ? pw : 0.0f;
            mq = in ? 0.0f : nw;
        }
        sm_mp[t] = mp; sm_mn[t] = mq;
    }

    int ci = t % 24, si = t / 24;
    bool active = (t < 264);

    float acc[4][8];
#pragma unroll
    for (int r = 0; r < 4; r++)
#pragma unroll
        for (int c = 0; c < 8; c++) acc[r][c] = 0.f;

    for (int chunk = 0; chunk < 2; chunk++) {
        __syncthreads();
        int k0 = chunk * 128;
        for (int i = t; i < 128 * 192; i += PB) {
            int k = i / 192, c = i % 192;
            float v;
            if (c < 64)       v = Wp1[(k0 + k) * 64 + c];
            else if (c < 128) v = Wq1[(k0 + k) * 64 + (c - 64)];
            else              v = Wa[(k0 + k) * 64 + (c - 128)];
            sm_w[i] = v;
        }
        __syncthreads();
        if (active) {
            int lbase = si * 4 * LSTR + k0;
            int wbase = ci * 8;
#pragma unroll 4
            for (int k = 0; k < 128; k++) {
                float4 w0 = *(const float4*)(sm_w + k * 192 + wbase);
                float4 w1 = *(const float4*)(sm_w + k * 192 + wbase + 4);
#pragma unroll
                for (int r = 0; r < 4; r++) {
                    float lv = sm_l[lbase + r * LSTR + k];
                    acc[r][0] += lv * w0.x; acc[r][1] += lv * w0.y;
                    acc[r][2] += lv * w0.z; acc[r][3] += lv * w0.w;
                    acc[r][4] += lv * w1.x; acc[r][5] += lv * w1.y;
                    acc[r][6] += lv * w1.z; acc[r][7] += lv * w1.w;
                }
            }
        }
    }

    // phase A: transform Z -> Hp/Hq in smem, and final-feature partials
    if (active) {
        int c0 = ci * 8;
        if (ci < 8) {
            float b[8];
#pragma unroll
            for (int c = 0; c < 8; c++) b[c] = bp1[c0 + c];
#pragma unroll
            for (int r = 0; r < 4; r++) {
                int s = si * 4 + r;
                float m = sm_mp[s];
#pragma unroll
                for (int c = 0; c < 8; c++)
                    sm_h[s * HSTR + c0 + c] = fast_tanh(m * acc[r][c] + b[c]);
            }
        } else if (ci < 16) {
            int cl = c0 - 64;
            float b[8];
#pragma unroll
            for (int c = 0; c < 8; c++) b[c] = bq1[cl + c];
#pragma unroll
            for (int r = 0; r < 4; r++) {
                int s = si * 4 + r;
                float m = sm_mn[s];
#pragma unroll
                for (int c = 0; c < 8; c++)
                    sm_h[s * HSTR + 64 + cl + c] = fast_tanh(m * acc[r][c] + b[c]);
            }
        } else {
            int cl = c0 - 128;
            float b[8], ps[8];
#pragma unroll
            for (int c = 0; c < 8; c++) { b[c] = ba[cl + c]; ps[c] = 0.f; }
#pragma unroll
            for (int r = 0; r < 4; r++) {
                int s = si * 4 + r;
                if (s < SEQ_) {
                    float m = sm_mp[s] + sm_mn[s];
#pragma unroll
                    for (int c = 0; c < 8; c++)
                        ps[c] += fast_tanh(m * acc[r][c] + b[c]);
                }
            }
#pragma unroll
            for (int c = 0; c < 8; c++) sm_red[si * 192 + 128 + cl + c] = ps[c];
        }
    }
    __syncthreads();

    // final-feature reduce + write
    if (t < 64) {
        float s = 0.f;
#pragma unroll
        for (int g = 0; g < 11; g++) s += sm_red[g * 192 + 128 + t];
        out_ff[n * 64 + t] = s * (1.0f / (float)SEQ_);
    }
    // stage W2s: sm_w[k*128 + c] = (c<64)? Wp2[k][c] : Wq2[k][c-64]
    for (int i = t; i < 64 * 128; i += PB) {
        int k = i >> 7, c = i & 127;
        sm_w[i] = (c < 64) ? Wp2[k * 64 + c] : Wq2[k * 64 + (c - 64)];
    }
    __syncthreads();

    // phase B: second-layer GEMM (ci<16), tanh, per-row partial sums
    float acc2[4][8];
#pragma unroll
    for (int r = 0; r < 4; r++)
#pragma unroll
        for (int c = 0; c < 8; c++) acc2[r][c] = 0.f;
    if (active && ci < 16) {
        int koff = (ci < 8) ? 0 : 64;
        int wbase = ci * 8;
#pragma unroll 4
        for (int k = 0; k < 64; k++) {
            float4 w0 = *(const float4*)(sm_w + k * 128 + wbase);
            float4 w1 = *(const float4*)(sm_w + k * 128 + wbase + 4);
#pragma unroll
            for (int r = 0; r < 4; r++) {
                float hv = sm_h[(si * 4 + r) * HSTR + koff + k];
                acc2[r][0] += hv * w0.x; acc2[r][1] += hv * w0.y;
                acc2[r][2] += hv * w0.z; acc2[r][3] += hv * w0.w;
                acc2[r][4] += hv * w1.x; acc2[r][5] += hv * w1.y;
                acc2[r][6] += hv * w1.z; acc2[r][7] += hv * w1.w;
            }
        }
        int c0 = ci * 8;
        const float* b2 = (ci < 8) ? bp2 : bq2;
        int cl = (ci < 8) ? c0 : c0 - 64;
        float b[8], ps[8];
#pragma unroll
        for (int c = 0; c < 8; c++) { b[c] = b2[cl + c]; ps[c] = 0.f; }
#pragma unroll
        for (int r = 0; r < 4; r++) {
            int s = si * 4 + r;
            if (s < SEQ_) {
#pragma unroll
                for (int c = 0; c < 8; c++)
                    ps[c] += fast_tanh(acc2[r][c] + b[c]);
            }
        }
#pragma unroll
        for (int c = 0; c < 8; c++) sm_red[si * 192 + c0 + c] = ps[c];
    }
    __syncthreads();

    // reduce to pos_vec / neg_vec + sq-norms
    if (t < 128) {
        float s = 0.f;
#pragma unroll
        for (int g = 0; g < 11; g++) s += sm_red[g * 192 + t];
        float v = s * (1.0f / (float)SEQ_);
        if (t < 64) g_posvec[n * 64 + t] = v;
        else        g_negvec[n * 64 + (t - 64)] = v;
        float sq = v * v;
#pragma unroll
        for (int o = 16; o; o >>= 1) sq += __shfl_xor_sync(0xffffffffu, sq, o);
        if ((t & 31) == 0) sm_ws[t >> 5] = sq;
    }
    __syncthreads();
    if (t == 0) {
        g_psn[n] = sm_ws[0] + sm_ws[1];
        g_nsn[n] = sm_ws[2] + sm_ws[3];
    }
}

// ---------------- K8: similarity sums (pos·pos and pos·neg) ----------------
// smem: pI[128*65], pJ[128*65], nJ[128*65], snI[128], snP[128], snN[128]
#define SIM_SMEM ((3 * 128 * 65 + 3 * 128) * 4)
__global__ void k_sims() {
    extern __shared__ float s[];
    float* pI = s;
    float* pJ = pI + 128 * 65;
    float* nJ = pJ + 128 * 65;
    float* snI = nJ + 128 * 65;
    float* snP = snI + 128;
    float* snN = snP + 128;
    __shared__ float rp[256], rn[256];

    int bi = blockIdx.y, bj = blockIdx.x, t = threadIdx.x;
    for (int i = t; i < 128 * 64; i += 256) {
        int r = i >> 6, k = i & 63;
        pI[r * 65 + k] = g_posvec[(bi * 128 + r) * 64 + k];
        pJ[r * 65 + k] = g_posvec[(bj * 128 + r) * 64 + k];
        nJ[r * 65 + k] = g_negvec[(bj * 128 + r) * 64 + k];
    }
    if (t < 128) { snI[t] = g_psn[bi * 128 + t]; }
    else { snP[t - 128] = g_psn[bj * 128 + (t - 128)]; }
    if (t < 128) snN[t] = g_nsn[bj * 128 + t];
    __syncthreads();

    int tx = t & 15, ty = t >> 4;
    float lp = 0.f, ln = 0.f;

    // pass 1: pos x pos
    {
        float acc[8][8];
#pragma unroll
        for (int r = 0; r < 8; r++)
#pragma unroll
            for (int c = 0; c < 8; c++) acc[r][c] = 0.f;
        for (int k = 0; k < 64; k++) {
            float a[8], b[8];
#pragma unroll
            for (int r = 0; r < 8; r++) a[r] = pI[(ty + 16 * r) * 65 + k];
#pragma unroll
            for (int c = 0; c < 8; c++) b[c] = pJ[(tx + 16 * c) * 65 + k];
#pragma unroll
            for (int r = 0; r < 8; r++)
#pragma unroll
                for (int c = 0; c < 8; c++) acc[r][c] += a[r] * b[c];
        }
#pragma unroll
        for (int r = 0; r < 8; r++)
#pragma unroll
            for (int c = 0; c < 8; c++) {
                float sq = snI[ty + 16 * r] + snP[tx + 16 * c] - 2.0f * acc[r][c];
                sq = fmaxf(sq, 0.0f);
                float d = (sq > 0.0f) ? sqrtf(sq) : 0.0f;
                lp += __expf(-d);
            }
    }
    // pass 2: pos x neg
    {
        float acc[8][8];
#pragma unroll
        for (int r = 0; r < 8; r++)
#pragma unroll
            for (int c = 0; c < 8; c++) acc[r][c] = 0.f;
        for (int k = 0; k < 64; k++) {
            float a[8], b[8];
#pragma unroll
            for (int r = 0; r < 8; r++) a[r] = pI[(ty + 16 * r) * 65 + k];
#pragma unroll
            for (int c = 0; c < 8; c++) b[c] = nJ[(tx + 16 * c) * 65 + k];
#pragma unroll
            for (int r = 0; r < 8; r++)
#pragma unroll
                for (int c = 0; c < 8; c++) acc[r][c] += a[r] * b[c];
        }
#pragma unroll
        for (int r = 0; r < 8; r++)
#pragma unroll
            for (int c = 0; c < 8; c++) {
                float sq = snI[ty + 16 * r] + snN[tx + 16 * c] - 2.0f * acc[r][c];
                sq = fmaxf(sq, 0.0f);
                float d = (sq > 0.0f) ? sqrtf(sq) : 0.0f;
                ln += __expf(-d);
            }
    }
    rp[t] = lp; rn[t] = ln;
    __syncthreads();
    for (int o = 128; o; o >>= 1) {
        if (t < o) { rp[t] += rp[t + o]; rn[t] += rn[t + o]; }
        __syncthreads();
    }
    if (t == 0) {
        int bid = bi * 32 + bj;
        g_sp[bid] = rp[0]; g_sn[bid] = rn[0];
    }
}

__global__ void k_loss(float* __restrict__ out_loss) {
    __shared__ float rp[1024], rn[1024];
    int t = threadIdx.x;
    rp[t] = g_sp[t]; rn[t] = g_sn[t];
    __syncthreads();
    for (int o = 512; o; o >>= 1) {
        if (t < o) { rp[t] += rp[t + o]; rn[t] += rn[t + o]; }
        __syncthreads();
    }
    if (t == 0) out_loss[0] = -logf(rp[0] / rn[0]);
}

// ---------------- launch ----------------
extern "C" void kernel_launch(void* const* d_in, const int* in_sizes, int n_in,
                              void* d_out, int out_size) {
    const float* A     = (const float*)d_in[0];
    const int*   C     = (const int*)d_in[1];
    const float* L     = (const float*)d_in[2];
    const float* W1    = (const float*)d_in[3];
    const float* b1    = (const float*)d_in[4];
    const float* gam   = (const float*)d_in[5];
    const float* bet   = (const float*)d_in[6];
    const float* sig   = (const float*)d_in[7];
    const float* Pw    = (const float*)d_in[8];
    const float* Nw    = (const float*)d_in[9];
    const float* Wp1   = (const float*)d_in[10];
    const float* bp1   = (const float*)d_in[11];
    const float* Wp2   = (const float*)d_in[12];
    const float* bp2   = (const float*)d_in[13];
    const float* Wq1   = (const float*)d_in[14];
    const float* bq1   = (const float*)d_in[15];
    const float* Wq2   = (const float*)d_in[16];
    const float* bq2   = (const float*)d_in[17];
    const float* Wa    = (const float*)d_in[18];
    const float* ba    = (const float*)d_in[19];

    float* out = (float*)d_out;
    float* out_ff   = out;                    // [4096*64]
    float* out_loss = out + N_ * RED_;        // [1]
    float* out_D    = out + N_ * RED_ + 1;    // [4096*4096]

    const int proj_smem = (SMW + SML + SMH + SMR + 44 + 44 + 8) * 4;
    cudaFuncSetAttribute(k_proj, cudaFuncAttributeMaxDynamicSharedMemorySize, proj_smem);
    cudaFuncSetAttribute(k_sims, cudaFuncAttributeMaxDynamicSharedMemorySize, SIM_SMEM);

    k_gather_h<<<N_, 128>>>(A, C, W1, b1);
    k_bnstats<<<1, 1024>>>();
    k_emb<<<512, 256>>>(gam, bet);
    k_dstats<<<dim3(32, 32), 256>>>(sig);
    k_dconsts<<<1, 1024>>>();
    k_dwrite<<<dim3(32, 32), 256>>>(sig, out_D);
    k_proj<<<N_, PB, proj_smem>>>(L, Pw, Nw, C, Wp1, bp1, Wp2, bp2,
                                  Wq1, bq1, Wq2, bq2, Wa, ba, out_ff);
    k_sims<<<dim3(32, 32), 256, SIM_SMEM>>>();
    k_loss<<<1, 1024>>>(out_loss);
}

// round 4
// speedup vs baseline: 2.7845x; 2.7845x over previous
#include <cuda_runtime.h>
#include <math.h>

#define N_   4096
#define SEQ_ 41
#define VEC_ 15
#define T_   8
#define EMB_ 32
#define LDIM_ 256
#define RED_ 64
#define M1_  (N_ * SEQ_)   // 167936 flat rows, 167936/128 = 1312 tiles

// ---------------- scratch (device globals; no allocation) ----------------
__device__ float g_h[N_ * EMB_];
__device__ float g_emb[N_ * EMB_];
__device__ float g_sqn[N_];
__device__ float g_mu[EMB_];
__device__ float g_rstd[EMB_];
__device__ float g_psum[1024];
__device__ float g_pmin[1024];
__device__ float g_pmax[1024];
__device__ float g_dc[3];            // avg, mn, inv
__device__ float g_posvec[N_ * RED_];
__device__ float g_negvec[N_ * RED_];
__device__ float g_psn[N_];
__device__ float g_nsn[N_];
__device__ float g_sp[1024];
__device__ float g_sn[1024];
// big scratch
__device__ float g_H[(size_t)M1_ * 128];    // Hp | Hq  (86 MB)
__device__ float g_TA[(size_t)M1_ * 64];    // tanh((mp+mn)*z_a + ba)  (43 MB)
__device__ float g_T2[(size_t)M1_ * 128];   // layer-2 tanh outputs (86 MB)
__device__ float g_Draw[(size_t)N_ * N_];   // raw exp vals (67 MB)

__device__ __forceinline__ float fast_tanh(float x) {
    float e = __expf(2.0f * x);
    return 1.0f - 2.0f / (e + 1.0f);
}

// ---------------- K1: gather + interp + h = tanh(flat@W1 + b1) ----------------
__global__ void k_gather_h(const float* __restrict__ A, const int* __restrict__ C,
                           const float* __restrict__ W1, const float* __restrict__ b1) {
    __shared__ float flat[120];
    int n = blockIdx.x;
    int t = threadIdx.x;
    int start = C[2 * n], end = C[2 * n + 1];
    int len = end - start + 1;
    if (t < 120) {
        int j = t / VEC_, v = t % VEC_;
        float scale = (float)len / (float)T_;
        float src = fmaxf(scale * ((float)j + 0.5f) - 0.5f, 0.0f);
        int i0 = min((int)floorf(src), len - 1);
        int i1 = min(i0 + 1, len - 1);
        float w = src - (float)i0;
        const float* Ar = A + (size_t)n * SEQ_ * VEC_;
        float g0 = Ar[(start + i0) * VEC_ + v];
        float g1 = Ar[(start + i1) * VEC_ + v];
        flat[t] = (1.0f - w) * g0 + w * g1;
    }
    __syncthreads();
    if (t < 32) {
        float acc = b1[t];
#pragma unroll
        for (int k = 0; k < 120; k++) acc += flat[k] * W1[k * 32 + t];
        g_h[n * 32 + t] = tanhf(acc);
    }
}

// ---------------- K2: batchnorm stats over N ----------------
__global__ void k_bnstats() {
    __shared__ float ssum[32][33];
    __shared__ float ssq[32][33];
    int c = threadIdx.x & 31, g = threadIdx.x >> 5;
    float s = 0.f, q = 0.f;
    for (int n = g; n < N_; n += 32) {
        float v = g_h[n * 32 + c];
        s += v; q += v * v;
    }
    ssum[g][c] = s; ssq[g][c] = q;
    __syncthreads();
    if (threadIdx.x < 32) {
        float S = 0.f, Q = 0.f;
        for (int gg = 0; gg < 32; gg++) { S += ssum[gg][threadIdx.x]; Q += ssq[gg][threadIdx.x]; }
        float mu = S / (float)N_;
        float var = Q / (float)N_ - mu * mu;
        g_mu[threadIdx.x] = mu;
        g_rstd[threadIdx.x] = rsqrtf(var + 1e-5f);
    }
}

// ---------------- K3: emb + row sq-norms ----------------
__global__ void k_emb(const float* __restrict__ gamma, const float* __restrict__ beta) {
    int idx = blockIdx.x * 256 + threadIdx.x;
    int c = idx & 31;
    float e = gamma[c] * (g_h[idx] - g_mu[c]) * g_rstd[c] + beta[c];
    g_emb[idx] = e;
    float sq = e * e;
#pragma unroll
    for (int o = 16; o; o >>= 1) sq += __shfl_xor_sync(0xffffffffu, sq, o);
    if (c == 0) g_sqn[idx >> 5] = sq;
}

// ---------------- D tile GEMM helper ----------------
__device__ __forceinline__ void d_tile_gemm(int bi, int bj, int t,
                                            float sI[128][33], float sJ[128][33],
                                            float snI[128], float snJ[128],
                                            float acc[8][8]) {
    for (int i = t; i < 128 * 32; i += 256) {
        int r = i >> 5, k = i & 31;
        sI[r][k] = g_emb[(bi * 128 + r) * 32 + k];
        sJ[r][k] = g_emb[(bj * 128 + r) * 32 + k];
    }
    if (t < 128) snI[t] = g_sqn[bi * 128 + t];
    else snJ[t - 128] = g_sqn[bj * 128 + (t - 128)];
    __syncthreads();
    int tx = t & 15, ty = t >> 4;
#pragma unroll
    for (int k = 0; k < 32; k++) {
        float a[8], b[8];
#pragma unroll
        for (int r = 0; r < 8; r++) a[r] = sI[ty + 16 * r][k];
#pragma unroll
        for (int c = 0; c < 8; c++) b[c] = sJ[tx + 16 * c][k];
#pragma unroll
        for (int r = 0; r < 8; r++)
#pragma unroll
            for (int c = 0; c < 8; c++) acc[r][c] += a[r] * b[c];
    }
}

// stats pass: also persists raw vals so the rewrite pass is elementwise
__global__ void k_dstats(const float* __restrict__ sigma_p) {
    __shared__ float sI[128][33], sJ[128][33];
    __shared__ float snI[128], snJ[128];
    __shared__ float rs[256], rmn[256], rmx[256];
    int bi = blockIdx.y, bj = blockIdx.x, t = threadIdx.x;
    float acc[8][8];
#pragma unroll
    for (int r = 0; r < 8; r++)
#pragma unroll
        for (int c = 0; c < 8; c++) acc[r][c] = 0.f;
    d_tile_gemm(bi, bj, t, sI, sJ, snI, snJ, acc);
    float inv2s;
    { float sg = sigma_p[0]; inv2s = 0.5f / (sg * sg); }
    int tx = t & 15, ty = t >> 4;
    float lsum = 0.f, lmin = 3.4e38f, lmax = -3.4e38f;
#pragma unroll
    for (int r = 0; r < 8; r++) {
        int gi = bi * 128 + ty + 16 * r;
#pragma unroll
        for (int c = 0; c < 8; c++) {
            int gj = bj * 128 + tx + 16 * c;
            float sq = snI[ty + 16 * r] + snJ[tx + 16 * c] - 2.0f * acc[r][c];
            sq = fmaxf(sq, 0.0f);
            float d = (sq > 0.0f) ? sqrtf(sq) : 0.0f;
            float val = __expf(-d * inv2s);
            g_Draw[(size_t)gi * N_ + gj] = val;
            if (gi != gj) { lsum += val; lmin = fminf(lmin, val); lmax = fmaxf(lmax, val); }
        }
    }
    rs[t] = lsum; rmn[t] = lmin; rmx[t] = lmax;
    __syncthreads();
    for (int o = 128; o; o >>= 1) {
        if (t < o) {
            rs[t] += rs[t + o];
            rmn[t] = fminf(rmn[t], rmn[t + o]);
            rmx[t] = fmaxf(rmx[t], rmx[t + o]);
        }
        __syncthreads();
    }
    if (t == 0) {
        int bid = bi * 32 + bj;
        g_psum[bid] = rs[0]; g_pmin[bid] = rmn[0]; g_pmax[bid] = rmx[0];
    }
}

__global__ void k_dconsts() {
    __shared__ float rs[1024], rmn[1024], rmx[1024];
    int t = threadIdx.x;
    rs[t] = g_psum[t]; rmn[t] = g_pmin[t]; rmx[t] = g_pmax[t];
    __syncthreads();
    for (int o = 512; o; o >>= 1) {
        if (t < o) {
            rs[t] += rs[t + o];
            rmn[t] = fminf(rmn[t], rmn[t + o]);
            rmx[t] = fmaxf(rmx[t], rmx[t + o]);
        }
        __syncthreads();
    }
    if (t == 0) {
        float avg = rs[0] / ((float)N_ * (float)(N_ - 1));
        float mn = (rmn[0] < avg) ? 0.0f : rmn[0];
        float mx = rmx[0];
        if (mx == mn) mx = mn + 1.0f;
        g_dc[0] = avg; g_dc[1] = mn; g_dc[2] = 1.0f / (mx - mn);
    }
}

// elementwise finalize of D (read raw vectorized, threshold + minmax, diag=1)
// NOTE: D output pointer is only 4-byte aligned (offset by the loss scalar),
// so stores MUST be scalar.
__global__ void k_dfinal(float* __restrict__ D) {
    float avg = g_dc[0], mn = g_dc[1], inv = g_dc[2];
    size_t base = ((size_t)blockIdx.x * 256 + threadIdx.x) * 4;
    float4 v = *(const float4*)(g_Draw + base);
    float vv[4] = { v.x, v.y, v.z, v.w };
#pragma unroll
    for (int j = 0; j < 4; j++) {
        size_t idx = base + j;
        int gi = (int)(idx >> 12);
        int gj = (int)(idx & 4095);
        float dt = (vv[j] < avg) ? 0.0f : vv[j];
        D[idx] = (gi == gj) ? 1.0f : (dt - mn) * inv;
    }
}

// ---------------- GEMM1: Z = Lflat[M1,256] @ [Wp1|Wq1|Wa]  + masked tanh epilogue -----
// tile 128(M) x 192(N), 384 threads, 8x8 micro (rows ty*4+{0..3}, 64+ty*4+{0..3};
// cols tx*4+{0..3}, 96+tx*4+{0..3}), k-major smem staging for float4 LDS.
__global__ void __launch_bounds__(384, 1)
k_gemm1(const float* __restrict__ L, const float* __restrict__ Pw,
        const float* __restrict__ Nw, const int* __restrict__ C,
        const float* __restrict__ Wp1, const float* __restrict__ bp1,
        const float* __restrict__ Wq1, const float* __restrict__ bq1,
        const float* __restrict__ Wa, const float* __restrict__ ba) {
    __shared__ float sA[32][132];
    __shared__ float sB[32][196];
    __shared__ float sMp[128], sMn[128];

    int t = threadIdx.x;
    int m0 = blockIdx.x * 128;
    int ty = t / 24, tx = t % 24;   // 16 x 24

    if (t < 128) {
        int m = m0 + t;
        int n = m / SEQ_, s = m - n * SEQ_;
        int st = C[2 * n], en = C[2 * n + 1];
        bool in = (s >= st && s <= en);
        sMp[t] = in ? Pw[n * SEQ_ + s] : 0.0f;
        sMn[t] = in ? 0.0f : Nw[n * SEQ_ + s];
    }

    float acc[8][8];
#pragma unroll
    for (int r = 0; r < 8; r++)
#pragma unroll
        for (int c = 0; c < 8; c++) acc[r][c] = 0.f;

    for (int kt = 0; kt < 8; kt++) {
        __syncthreads();
        // stage A (transpose to k-major): 128 rows x 32 k
        for (int i = t; i < 1024; i += 384) {
            int r = i >> 3, k4 = (i & 7) * 4;
            float4 v = *(const float4*)(L + (size_t)(m0 + r) * 256 + kt * 32 + k4);
            sA[k4 + 0][r] = v.x; sA[k4 + 1][r] = v.y;
            sA[k4 + 2][r] = v.z; sA[k4 + 3][r] = v.w;
        }
        // stage B: 32 k x 192 cols (Wp1 | Wq1 | Wa)
        for (int i = t; i < 32 * 48; i += 384) {
            int k = i / 48, c4 = (i % 48) * 4;
            int gk = kt * 32 + k;
            float4 v;
            if (c4 < 64)       v = *(const float4*)(Wp1 + gk * 64 + c4);
            else if (c4 < 128) v = *(const float4*)(Wq1 + gk * 64 + (c4 - 64));
            else               v = *(const float4*)(Wa + gk * 64 + (c4 - 128));
            *(float4*)(&sB[k][c4]) = v;
        }
        __syncthreads();
#pragma unroll
        for (int k = 0; k < 32; k++) {
            float4 a0 = *(const float4*)&sA[k][ty * 4];
            float4 a1 = *(const float4*)&sA[k][64 + ty * 4];
            float4 b0 = *(const float4*)&sB[k][tx * 4];
            float4 b1 = *(const float4*)&sB[k][96 + tx * 4];
            float av[8] = { a0.x, a0.y, a0.z, a0.w, a1.x, a1.y, a1.z, a1.w };
            float bv[8] = { b0.x, b0.y, b0.z, b0.w, b1.x, b1.y, b1.z, b1.w };
#pragma unroll
            for (int r = 0; r < 8; r++)
#pragma unroll
                for (int c = 0; c < 8; c++) acc[r][c] += av[r] * bv[c];
        }
    }

    // epilogue
    int c0 = tx * 4;        // [0,96): P if <64 else Q
    int c1 = 96 + tx * 4;   // [96,192): Q if <128 else A
    int g0q = (c0 >= 64);
    int g1a = (c1 >= 128);
    float bh0[4], bh1[4];
#pragma unroll
    for (int j = 0; j < 4; j++) {
        bh0[j] = g0q ? bq1[c0 - 64 + j] : bp1[c0 + j];
        bh1[j] = g1a ? ba[c1 - 128 + j] : bq1[c1 - 64 + j];
    }
#pragma unroll
    for (int r = 0; r < 8; r++) {
        int row = (r < 4) ? (ty * 4 + r) : (64 + ty * 4 + (r - 4));
        size_t m = (size_t)(m0 + row);
        float mp = sMp[row], mn = sMn[row];
        float sc0 = g0q ? mn : mp;
        float4 o0;
        o0.x = fast_tanh(sc0 * acc[r][0] + bh0[0]);
        o0.y = fast_tanh(sc0 * acc[r][1] + bh0[1]);
        o0.z = fast_tanh(sc0 * acc[r][2] + bh0[2]);
        o0.w = fast_tanh(sc0 * acc[r][3] + bh0[3]);
        *(float4*)(g_H + m * 128 + c0) = o0;
        if (!g1a) {
            float4 o1;
            o1.x = fast_tanh(mn * acc[r][4] + bh1[0]);
            o1.y = fast_tanh(mn * acc[r][5] + bh1[1]);
            o1.z = fast_tanh(mn * acc[r][6] + bh1[2]);
            o1.w = fast_tanh(mn * acc[r][7] + bh1[3]);
            *(float4*)(g_H + m * 128 + c1) = o1;
        } else {
            float sc = mp + mn;
            float4 o1;
            o1.x = fast_tanh(sc * acc[r][4] + bh1[0]);
            o1.y = fast_tanh(sc * acc[r][5] + bh1[1]);
            o1.z = fast_tanh(sc * acc[r][6] + bh1[2]);
            o1.w = fast_tanh(sc * acc[r][7] + bh1[3]);
            *(float4*)(g_TA + m * 64 + (c1 - 128)) = o1;
        }
    }
}

// ---------------- GEMM2: per path p/q: T2 = tanh(H[:,koff:koff+64] @ W2 + b2) -------
// grid (1312, 2), 256 threads, tile 128x64, 8x4 micro, KT=32 x 2 tiles
__global__ void __launch_bounds__(256)
k_gemm2(const float* __restrict__ Wp2, const float* __restrict__ bp2,
        const float* __restrict__ Wq2, const float* __restrict__ bq2) {
    __shared__ float sA[32][132];
    __shared__ float sB[32][68];
    int t = threadIdx.x;
    int m0 = blockIdx.x * 128;
    int path = blockIdx.y;
    int koff = path * 64;
    const float* W2 = path ? Wq2 : Wp2;
    const float* b2 = path ? bq2 : bp2;
    int ty = t / 16, tx = t % 16;

    float acc[8][4];
#pragma unroll
    for (int r = 0; r < 8; r++)
#pragma unroll
        for (int c = 0; c < 4; c++) acc[r][c] = 0.f;

    for (int kt = 0; kt < 2; kt++) {
        __syncthreads();
        for (int i = t; i < 1024; i += 256) {   // 128 rows x 8 float4
            int r = i >> 3, k4 = (i & 7) * 4;
            float4 v = *(const float4*)(g_H + (size_t)(m0 + r) * 128 + koff + kt * 32 + k4);
            sA[k4 + 0][r] = v.x; sA[k4 + 1][r] = v.y;
            sA[k4 + 2][r] = v.z; sA[k4 + 3][r] = v.w;
        }
        for (int i = t; i < 32 * 16; i += 256) {
            int k = i >> 4, c4 = (i & 15) * 4;
            float4 v = *(const float4*)(W2 + (kt * 32 + k) * 64 + c4);
            *(float4*)(&sB[k][c4]) = v;
        }
        __syncthreads();
#pragma unroll
        for (int k = 0; k < 32; k++) {
            float4 a0 = *(const float4*)&sA[k][ty * 4];
            float4 a1 = *(const float4*)&sA[k][64 + ty * 4];
            float4 b0 = *(const float4*)&sB[k][tx * 4];
            float av[8] = { a0.x, a0.y, a0.z, a0.w, a1.x, a1.y, a1.z, a1.w };
            float bv[4] = { b0.x, b0.y, b0.z, b0.w };
#pragma unroll
            for (int r = 0; r < 8; r++)
#pragma unroll
                for (int c = 0; c < 4; c++) acc[r][c] += av[r] * bv[c];
        }
    }

    int c0 = tx * 4;
    float bb[4];
#pragma unroll
    for (int j = 0; j < 4; j++) bb[j] = b2[c0 + j];
#pragma unroll
    for (int r = 0; r < 8; r++) {
        int row = (r < 4) ? (ty * 4 + r) : (64 + ty * 4 + (r - 4));
        size_t m = (size_t)(m0 + row);
        float4 o;
        o.x = fast_tanh(acc[r][0] + bb[0]);
        o.y = fast_tanh(acc[r][1] + bb[1]);
        o.z = fast_tanh(acc[r][2] + bb[2]);
        o.w = fast_tanh(acc[r][3] + bb[3]);
        *(float4*)(g_T2 + m * 128 + koff + c0) = o;
    }
}

// ---------------- R1: final_feature mean ----------------
__global__ void k_r1(float* __restrict__ out_ff) {
    int n = blockIdx.x, t = threadIdx.x;   // 64 threads
    float s = 0.f;
#pragma unroll 8
    for (int q = 0; q < SEQ_; q++) s += g_TA[((size_t)n * SEQ_ + q) * 64 + t];
    out_ff[n * 64 + t] = s * (1.0f / (float)SEQ_);
}

// ---------------- R2: pos/neg vec means + sq-norms ----------------
__global__ void k_r2() {
    __shared__ float ws[4];
    int n = blockIdx.x, t = threadIdx.x;   // 128 threads
    float s = 0.f;
#pragma unroll 8
    for (int q = 0; q < SEQ_; q++) s += g_T2[((size_t)n * SEQ_ + q) * 128 + t];
    float v = s * (1.0f / (float)SEQ_);
    if (t < 64) g_posvec[n * 64 + t] = v;
    else        g_negvec[n * 64 + (t - 64)] = v;
    float sq = v * v;
#pragma unroll
    for (int o = 16; o; o >>= 1) sq += __shfl_xor_sync(0xffffffffu, sq, o);
    if ((t & 31) == 0) ws[t >> 5] = sq;
    __syncthreads();
    if (t == 0) {
        g_psn[n] = ws[0] + ws[1];
        g_nsn[n] = ws[2] + ws[3];
    }
}

// ---------------- K8: similarity sums ----------------
#define SIM_SMEM ((3 * 128 * 65 + 3 * 128) * 4)
__global__ void k_sims() {
    extern __shared__ float s[];
    float* pI = s;
    float* pJ = pI + 128 * 65;
    float* nJ = pJ + 128 * 65;
    float* snI = nJ + 128 * 65;
    float* snP = snI + 128;
    float* snN = snP + 128;
    __shared__ float rp[256], rn[256];

    int bi = blockIdx.y, bj = blockIdx.x, t = threadIdx.x;
    for (int i = t; i < 128 * 64; i += 256) {
        int r = i >> 6, k = i & 63;
        pI[r * 65 + k] = g_posvec[(bi * 128 + r) * 64 + k];
        pJ[r * 65 + k] = g_posvec[(bj * 128 + r) * 64 + k];
        nJ[r * 65 + k] = g_negvec[(bj * 128 + r) * 64 + k];
    }
    if (t < 128) { snI[t] = g_psn[bi * 128 + t]; }
    else { snP[t - 128] = g_psn[bj * 128 + (t - 128)]; }
    if (t < 128) snN[t] = g_nsn[bj * 128 + t];
    __syncthreads();

    int tx = t & 15, ty = t >> 4;
    float lp = 0.f, ln = 0.f;
    {
        float acc[8][8];
#pragma unroll
        for (int r = 0; r < 8; r++)
#pragma unroll
            for (int c = 0; c < 8; c++) acc[r][c] = 0.f;
        for (int k = 0; k < 64; k++) {
            float a[8], b[8];
#pragma unroll
            for (int r = 0; r < 8; r++) a[r] = pI[(ty + 16 * r) * 65 + k];
#pragma unroll
            for (int c = 0; c < 8; c++) b[c] = pJ[(tx + 16 * c) * 65 + k];
#pragma unroll
            for (int r = 0; r < 8; r++)
#pragma unroll
                for (int c = 0; c < 8; c++) acc[r][c] += a[r] * b[c];
        }
#pragma unroll
        for (int r = 0; r < 8; r++)
#pragma unroll
            for (int c = 0; c < 8; c++) {
                float sq = snI[ty + 16 * r] + snP[tx + 16 * c] - 2.0f * acc[r][c];
                sq = fmaxf(sq, 0.0f);
                float d = (sq > 0.0f) ? sqrtf(sq) : 0.0f;
                lp += __expf(-d);
            }
    }
    {
        float acc[8][8];
#pragma unroll
        for (int r = 0; r < 8; r++)
#pragma unroll
            for (int c = 0; c < 8; c++) acc[r][c] = 0.f;
        for (int k = 0; k < 64; k++) {
            float a[8], b[8];
#pragma unroll
            for (int r = 0; r < 8; r++) a[r] = pI[(ty + 16 * r) * 65 + k];
#pragma unroll
            for (int c = 0; c < 8; c++) b[c] = nJ[(tx + 16 * c) * 65 + k];
#pragma unroll
            for (int r = 0; r < 8; r++)
#pragma unroll
                for (int c = 0; c < 8; c++) acc[r][c] += a[r] * b[c];
        }
#pragma unroll
        for (int r = 0; r < 8; r++)
#pragma unroll
            for (int c = 0; c < 8; c++) {
                float sq = snI[ty + 16 * r] + snN[tx + 16 * c] - 2.0f * acc[r][c];
                sq = fmaxf(sq, 0.0f);
                float d = (sq > 0.0f) ? sqrtf(sq) : 0.0f;
                ln += __expf(-d);
            }
    }
    rp[t] = lp; rn[t] = ln;
    __syncthreads();
    for (int o = 128; o; o >>= 1) {
        if (t < o) { rp[t] += rp[t + o]; rn[t] += rn[t + o]; }
        __syncthreads();
    }
    if (t == 0) {
        int bid = bi * 32 + bj;
        g_sp[bid] = rp[0]; g_sn[bid] = rn[0];
    }
}

__global__ void k_loss(float* __restrict__ out_loss) {
    __shared__ float rp[1024], rn[1024];
    int t = threadIdx.x;
    rp[t] = g_sp[t]; rn[t] = g_sn[t];
    __syncthreads();
    for (int o = 512; o; o >>= 1) {
        if (t < o) { rp[t] += rp[t + o]; rn[t] += rn[t + o]; }
        __syncthreads();
    }
    if (t == 0) out_loss[0] = -logf(rp[0] / rn[0]);
}

// ---------------- launch ----------------
extern "C" void kernel_launch(void* const* d_in, const int* in_sizes, int n_in,
                              void* d_out, int out_size) {
    const float* A     = (const float*)d_in[0];
    const int*   C     = (const int*)d_in[1];
    const float* L     = (const float*)d_in[2];
    const float* W1    = (const float*)d_in[3];
    const float* b1    = (const float*)d_in[4];
    const float* gam   = (const float*)d_in[5];
    const float* bet   = (const float*)d_in[6];
    const float* sig   = (const float*)d_in[7];
    const float* Pw    = (const float*)d_in[8];
    const float* Nw    = (const float*)d_in[9];
    const float* Wp1   = (const float*)d_in[10];
    const float* bp1   = (const float*)d_in[11];
    const float* Wp2   = (const float*)d_in[12];
    const float* bp2   = (const float*)d_in[13];
    const float* Wq1   = (const float*)d_in[14];
    const float* bq1   = (const float*)d_in[15];
    const float* Wq2   = (const float*)d_in[16];
    const float* bq2   = (const float*)d_in[17];
    const float* Wa    = (const float*)d_in[18];
    const float* ba    = (const float*)d_in[19];

    float* out = (float*)d_out;
    float* out_ff   = out;                    // [4096*64]
    float* out_loss = out + N_ * RED_;        // [1]
    float* out_D    = out + N_ * RED_ + 1;    // [4096*4096], only 4B-aligned!

    cudaFuncSetAttribute(k_sims, cudaFuncAttributeMaxDynamicSharedMemorySize, SIM_SMEM);

    k_gather_h<<<N_, 128>>>(A, C, W1, b1);
    k_bnstats<<<1, 1024>>>();
    k_emb<<<512, 256>>>(gam, bet);
    k_dstats<<<dim3(32, 32), 256>>>(sig);
    k_dconsts<<<1, 1024>>>();
    k_dfinal<<<(N_ * (N_ / 4)) / 256, 256>>>(out_D);
    k_gemm1<<<M1_ / 128, 384>>>(L, Pw, Nw, C, Wp1, bp1, Wq1, bq1, Wa, ba);
    k_gemm2<<<dim3(M1_ / 128, 2), 256>>>(Wp2, bp2, Wq2, bq2);
    k_r1<<<N_, 64>>>(out_ff);
    k_r2<<<N_, 128>>>();
    k_sims<<<dim3(32, 32), 256, SIM_SMEM>>>();
    k_loss<<<1, 1024>>>(out_loss);
}

// round 7
// speedup vs baseline: 2.8437x; 1.0213x over previous
#include <cuda_runtime.h>
#include <math.h>

#define N_   4096
#define SEQ_ 41
#define VEC_ 15
#define T_   8
#define EMB_ 32
#define LDIM_ 256
#define RED_ 64
#define M1_  (N_ * SEQ_)   // 167936 flat rows, 167936/128 = 1312 tiles

// ---------------- scratch (device globals; no allocation) ----------------
__device__ float g_h[N_ * EMB_];
__device__ float g_emb[N_ * EMB_];
__device__ float g_sqn[N_];
__device__ float g_mu[EMB_];
__device__ float g_rstd[EMB_];
__device__ float g_psum[1024];
__device__ float g_pmin[1024];
__device__ float g_pmax[1024];
__device__ float g_dc[3];            // avg, mn, inv
__device__ float g_posvec[N_ * RED_];
__device__ float g_negvec[N_ * RED_];
__device__ float g_psn[N_];
__device__ float g_nsn[N_];
__device__ float g_sp[1024];
__device__ float g_sn[1024];
// big scratch
__device__ float g_H[(size_t)M1_ * 128];    // Hp | Hq  (86 MB)
__device__ float g_TA[(size_t)M1_ * 64];    // tanh((mp+mn)*z_a + ba)  (43 MB)
__device__ float g_T2[(size_t)M1_ * 128];   // layer-2 tanh outputs (86 MB)
__device__ float g_Draw[(size_t)N_ * N_];   // raw exp vals (67 MB)

__device__ __forceinline__ float fast_tanh(float x) {
    float e = __expf(2.0f * x);
    return 1.0f - 2.0f / (e + 1.0f);
}

// ---- packed fp32x2 helpers (FFMA2: 2 exact fp32 FMAs per instruction) ----
__device__ __forceinline__ void ffma2(unsigned long long& d,
                                      unsigned long long a,
                                      unsigned long long b) {
    asm("fma.rn.f32x2 %0, %1, %2, %0;" : "+l"(d) : "l"(a), "l"(b));
}
__device__ __forceinline__ unsigned long long dup2(float x) {
    unsigned long long r;
    asm("mov.b64 %0, {%1, %1};" : "=l"(r) : "f"(x));
    return r;
}
__device__ __forceinline__ void unpack2(unsigned long long v, float& lo, float& hi) {
    asm("mov.b64 {%0, %1}, %2;" : "=f"(lo), "=f"(hi) : "l"(v));
}

// ---------------- K1: gather + interp + h = tanh(flat@W1 + b1) ----------------
__global__ void k_gather_h(const float* __restrict__ A, const int* __restrict__ C,
                           const float* __restrict__ W1, const float* __restrict__ b1) {
    __shared__ float flat[120];
    int n = blockIdx.x;
    int t = threadIdx.x;
    int start = C[2 * n], end = C[2 * n + 1];
    int len = end - start + 1;
    if (t < 120) {
        int j = t / VEC_, v = t % VEC_;
        float scale = (float)len / (float)T_;
        float src = fmaxf(scale * ((float)j + 0.5f) - 0.5f, 0.0f);
        int i0 = min((int)floorf(src), len - 1);
        int i1 = min(i0 + 1, len - 1);
        float w = src - (float)i0;
        const float* Ar = A + (size_t)n * SEQ_ * VEC_;
        float g0 = Ar[(start + i0) * VEC_ + v];
        float g1 = Ar[(start + i1) * VEC_ + v];
        flat[t] = (1.0f - w) * g0 + w * g1;
    }
    __syncthreads();
    if (t < 32) {
        float acc = b1[t];
#pragma unroll
        for (int k = 0; k < 120; k++) acc += flat[k] * W1[k * 32 + t];
        g_h[n * 32 + t] = tanhf(acc);
    }
}

// ---------------- K2: batchnorm stats over N ----------------
__global__ void k_bnstats() {
    __shared__ float ssum[32][33];
    __shared__ float ssq[32][33];
    int c = threadIdx.x & 31, g = threadIdx.x >> 5;
    float s = 0.f, q = 0.f;
    for (int n = g; n < N_; n += 32) {
        float v = g_h[n * 32 + c];
        s += v; q += v * v;
    }
    ssum[g][c] = s; ssq[g][c] = q;
    __syncthreads();
    if (threadIdx.x < 32) {
        float S = 0.f, Q = 0.f;
        for (int gg = 0; gg < 32; gg++) { S += ssum[gg][threadIdx.x]; Q += ssq[gg][threadIdx.x]; }
        float mu = S / (float)N_;
        float var = Q / (float)N_ - mu * mu;
        g_mu[threadIdx.x] = mu;
        g_rstd[threadIdx.x] = rsqrtf(var + 1e-5f);
    }
}

// ---------------- K3: emb + row sq-norms ----------------
__global__ void k_emb(const float* __restrict__ gamma, const float* __restrict__ beta) {
    int idx = blockIdx.x * 256 + threadIdx.x;
    int c = idx & 31;
    float e = gamma[c] * (g_h[idx] - g_mu[c]) * g_rstd[c] + beta[c];
    g_emb[idx] = e;
    float sq = e * e;
#pragma unroll
    for (int o = 16; o; o >>= 1) sq += __shfl_xor_sync(0xffffffffu, sq, o);
    if (c == 0) g_sqn[idx >> 5] = sq;
}

// ---------------- D tile GEMM helper ----------------
__device__ __forceinline__ void d_tile_gemm(int bi, int bj, int t,
                                            float sI[128][33], float sJ[128][33],
                                            float snI[128], float snJ[128],
                                            float acc[8][8]) {
    for (int i = t; i < 128 * 32; i += 256) {
        int r = i >> 5, k = i & 31;
        sI[r][k] = g_emb[(bi * 128 + r) * 32 + k];
        sJ[r][k] = g_emb[(bj * 128 + r) * 32 + k];
    }
    if (t < 128) snI[t] = g_sqn[bi * 128 + t];
    else snJ[t - 128] = g_sqn[bj * 128 + (t - 128)];
    __syncthreads();
    int tx = t & 15, ty = t >> 4;
#pragma unroll
    for (int k = 0; k < 32; k++) {
        float a[8], b[8];
#pragma unroll
        for (int r = 0; r < 8; r++) a[r] = sI[ty + 16 * r][k];
#pragma unroll
        for (int c = 0; c < 8; c++) b[c] = sJ[tx + 16 * c][k];
#pragma unroll
        for (int r = 0; r < 8; r++)
#pragma unroll
            for (int c = 0; c < 8; c++) acc[r][c] += a[r] * b[c];
    }
}

// stats pass: also persists raw vals so the rewrite pass is elementwise
__global__ void k_dstats(const float* __restrict__ sigma_p) {
    __shared__ float sI[128][33], sJ[128][33];
    __shared__ float snI[128], snJ[128];
    __shared__ float rs[256], rmn[256], rmx[256];
    int bi = blockIdx.y, bj = blockIdx.x, t = threadIdx.x;
    float acc[8][8];
#pragma unroll
    for (int r = 0; r < 8; r++)
#pragma unroll
        for (int c = 0; c < 8; c++) acc[r][c] = 0.f;
    d_tile_gemm(bi, bj, t, sI, sJ, snI, snJ, acc);
    float inv2s;
    { float sg = sigma_p[0]; inv2s = 0.5f / (sg * sg); }
    int tx = t & 15, ty = t >> 4;
    float lsum = 0.f, lmin = 3.4e38f, lmax = -3.4e38f;
#pragma unroll
    for (int r = 0; r < 8; r++) {
        int gi = bi * 128 + ty + 16 * r;
#pragma unroll
        for (int c = 0; c < 8; c++) {
            int gj = bj * 128 + tx + 16 * c;
            float sq = snI[ty + 16 * r] + snJ[tx + 16 * c] - 2.0f * acc[r][c];
            sq = fmaxf(sq, 0.0f);
            float d = (sq > 0.0f) ? sqrtf(sq) : 0.0f;
            float val = __expf(-d * inv2s);
            g_Draw[(size_t)gi * N_ + gj] = val;
            if (gi != gj) { lsum += val; lmin = fminf(lmin, val); lmax = fmaxf(lmax, val); }
        }
    }
    rs[t] = lsum; rmn[t] = lmin; rmx[t] = lmax;
    __syncthreads();
    for (int o = 128; o; o >>= 1) {
        if (t < o) {
            rs[t] += rs[t + o];
            rmn[t] = fminf(rmn[t], rmn[t + o]);
            rmx[t] = fmaxf(rmx[t], rmx[t + o]);
        }
        __syncthreads();
    }
    if (t == 0) {
        int bid = bi * 32 + bj;
        g_psum[bid] = rs[0]; g_pmin[bid] = rmn[0]; g_pmax[bid] = rmx[0];
    }
}

__global__ void k_dconsts() {
    __shared__ float rs[1024], rmn[1024], rmx[1024];
    int t = threadIdx.x;
    rs[t] = g_psum[t]; rmn[t] = g_pmin[t]; rmx[t] = g_pmax[t];
    __syncthreads();
    for (int o = 512; o; o >>= 1) {
        if (t < o) {
            rs[t] += rs[t + o];
            rmn[t] = fminf(rmn[t], rmn[t + o]);
            rmx[t] = fmaxf(rmx[t], rmx[t + o]);
        }
        __syncthreads();
    }
    if (t == 0) {
        float avg = rs[0] / ((float)N_ * (float)(N_ - 1));
        float mn = (rmn[0] < avg) ? 0.0f : rmn[0];
        float mx = rmx[0];
        if (mx == mn) mx = mn + 1.0f;
        g_dc[0] = avg; g_dc[1] = mn; g_dc[2] = 1.0f / (mx - mn);
    }
}

// elementwise finalize of D. D output pointer is only 4B-aligned -> scalar stores.
__global__ void k_dfinal(float* __restrict__ D) {
    float avg = g_dc[0], mn = g_dc[1], inv = g_dc[2];
    size_t base = ((size_t)blockIdx.x * 256 + threadIdx.x) * 4;
    float4 v = *(const float4*)(g_Draw + base);
    float vv[4] = { v.x, v.y, v.z, v.w };
#pragma unroll
    for (int j = 0; j < 4; j++) {
        size_t idx = base + j;
        int gi = (int)(idx >> 12);
        int gj = (int)(idx & 4095);
        float dt = (vv[j] < avg) ? 0.0f : vv[j];
        D[idx] = (gi == gj) ? 1.0f : (dt - mn) * inv;
    }
}

// ---------------- GEMM1: Z = Lflat[M1,256] @ [Wp1|Wq1|Wa]  + masked tanh epilogue -----
// tile 128(M) x 192(N), 384 threads, 8x8 micro; inner loop on packed f32x2 (FFMA2).
__global__ void __launch_bounds__(384, 1)
k_gemm1(const float* __restrict__ L, const float* __restrict__ Pw,
        const float* __restrict__ Nw, const int* __restrict__ C,
        const float* __restrict__ Wp1, const float* __restrict__ bp1,
        const float* __restrict__ Wq1, const float* __restrict__ bq1,
        const float* __restrict__ Wa, const float* __restrict__ ba) {
    __shared__ float sA[32][132];
    __shared__ float sB[32][196];
    __shared__ float sMp[128], sMn[128];

    int t = threadIdx.x;
    int m0 = blockIdx.x * 128;
    int ty = t / 24, tx = t % 24;   // 16 x 24

    if (t < 128) {
        int m = m0 + t;
        int n = m / SEQ_, s = m - n * SEQ_;
        int st = C[2 * n], en = C[2 * n + 1];
        bool in = (s >= st && s <= en);
        sMp[t] = in ? Pw[n * SEQ_ + s] : 0.0f;
        sMn[t] = in ? 0.0f : Nw[n * SEQ_ + s];
    }

    // accP[r][cp]: lane0 = col 2*cp, lane1 = col 2*cp+1 within the two 4-col groups
    unsigned long long accP[8][4];
#pragma unroll
    for (int r = 0; r < 8; r++)
#pragma unroll
        for (int c = 0; c < 4; c++) accP[r][c] = 0ull;

    for (int kt = 0; kt < 8; kt++) {
        __syncthreads();
        // stage A (transpose to k-major): 128 rows x 32 k
        for (int i = t; i < 1024; i += 384) {
            int r = i >> 3, k4 = (i & 7) * 4;
            float4 v = *(const float4*)(L + (size_t)(m0 + r) * 256 + kt * 32 + k4);
            sA[k4 + 0][r] = v.x; sA[k4 + 1][r] = v.y;
            sA[k4 + 2][r] = v.z; sA[k4 + 3][r] = v.w;
        }
        // stage B: 32 k x 192 cols (Wp1 | Wq1 | Wa)
        for (int i = t; i < 32 * 48; i += 384) {
            int k = i / 48, c4 = (i % 48) * 4;
            int gk = kt * 32 + k;
            float4 v;
            if (c4 < 64)       v = *(const float4*)(Wp1 + gk * 64 + c4);
            else if (c4 < 128) v = *(const float4*)(Wq1 + gk * 64 + (c4 - 64));
            else               v = *(const float4*)(Wa + gk * 64 + (c4 - 128));
            *(float4*)(&sB[k][c4]) = v;
        }
        __syncthreads();
#pragma unroll
        for (int k = 0; k < 32; k++) {
            float4 a0 = *(const float4*)&sA[k][ty * 4];
            float4 a1 = *(const float4*)&sA[k][64 + ty * 4];
            ulonglong2 b0 = *(const ulonglong2*)&sB[k][tx * 4];
            ulonglong2 b1 = *(const ulonglong2*)&sB[k][96 + tx * 4];
            float av[8] = { a0.x, a0.y, a0.z, a0.w, a1.x, a1.y, a1.z, a1.w };
            unsigned long long bp[4] = { b0.x, b0.y, b1.x, b1.y };
#pragma unroll
            for (int r = 0; r < 8; r++) {
                unsigned long long ad = dup2(av[r]);
#pragma unroll
                for (int c = 0; c < 4; c++) ffma2(accP[r][c], ad, bp[c]);
            }
        }
    }

    // unpack
    float acc[8][8];
#pragma unroll
    for (int r = 0; r < 8; r++)
#pragma unroll
        for (int c = 0; c < 4; c++) unpack2(accP[r][c], acc[r][2 * c], acc[r][2 * c + 1]);

    // epilogue
    int c0 = tx * 4;        // [0,96): P if <64 else Q
    int c1 = 96 + tx * 4;   // [96,192): Q if <128 else A
    int g0q = (c0 >= 64);
    int g1a = (c1 >= 128);
    float bh0[4], bh1[4];
#pragma unroll
    for (int j = 0; j < 4; j++) {
        bh0[j] = g0q ? bq1[c0 - 64 + j] : bp1[c0 + j];
        bh1[j] = g1a ? ba[c1 - 128 + j] : bq1[c1 - 64 + j];
    }
#pragma unroll
    for (int r = 0; r < 8; r++) {
        int row = (r < 4) ? (ty * 4 + r) : (64 + ty * 4 + (r - 4));
        size_t m = (size_t)(m0 + row);
        float mp = sMp[row], mn = sMn[row];
        float sc0 = g0q ? mn : mp;
        float4 o0;
        o0.x = fast_tanh(sc0 * acc[r][0] + bh0[0]);
        o0.y = fast_tanh(sc0 * acc[r][1] + bh0[1]);
        o0.z = fast_tanh(sc0 * acc[r][2] + bh0[2]);
        o0.w = fast_tanh(sc0 * acc[r][3] + bh0[3]);
        *(float4*)(g_H + m * 128 + c0) = o0;
        if (!g1a) {
            float4 o1;
            o1.x = fast_tanh(mn * acc[r][4] + bh1[0]);
            o1.y = fast_tanh(mn * acc[r][5] + bh1[1]);
            o1.z = fast_tanh(mn * acc[r][6] + bh1[2]);
            o1.w = fast_tanh(mn * acc[r][7] + bh1[3]);
            *(float4*)(g_H + m * 128 + c1) = o1;
        } else {
            float sc = mp + mn;
            float4 o1;
            o1.x = fast_tanh(sc * acc[r][4] + bh1[0]);
            o1.y = fast_tanh(sc * acc[r][5] + bh1[1]);
            o1.z = fast_tanh(sc * acc[r][6] + bh1[2]);
            o1.w = fast_tanh(sc * acc[r][7] + bh1[3]);
            *(float4*)(g_TA + m * 64 + (c1 - 128)) = o1;
        }
    }
}

// ---------------- GEMM2: per path p/q: T2 = tanh(H[:,koff:koff+64] @ W2 + b2) -------
// grid (1312, 2), 256 threads, tile 128x64, 8x4 micro, f32x2 inner loop
__global__ void __launch_bounds__(256)
k_gemm2(const float* __restrict__ Wp2, const float* __restrict__ bp2,
        const float* __restrict__ Wq2, const float* __restrict__ bq2) {
    __shared__ float sA[32][132];
    __shared__ float sB[32][68];
    int t = threadIdx.x;
    int m0 = blockIdx.x * 128;
    int path = blockIdx.y;
    int koff = path * 64;
    const float* W2 = path ? Wq2 : Wp2;
    const float* b2 = path ? bq2 : bp2;
    int ty = t / 16, tx = t % 16;

    unsigned long long accP[8][2];
#pragma unroll
    for (int r = 0; r < 8; r++)
#pragma unroll
        for (int c = 0; c < 2; c++) accP[r][c] = 0ull;

    for (int kt = 0; kt < 2; kt++) {
        __syncthreads();
        for (int i = t; i < 1024; i += 256) {   // 128 rows x 8 float4
            int r = i >> 3, k4 = (i & 7) * 4;
            float4 v = *(const float4*)(g_H + (size_t)(m0 + r) * 128 + koff + kt * 32 + k4);
            sA[k4 + 0][r] = v.x; sA[k4 + 1][r] = v.y;
            sA[k4 + 2][r] = v.z; sA[k4 + 3][r] = v.w;
        }
        for (int i = t; i < 32 * 16; i += 256) {
            int k = i >> 4, c4 = (i & 15) * 4;
            float4 v = *(const float4*)(W2 + (kt * 32 + k) * 64 + c4);
            *(float4*)(&sB[k][c4]) = v;
        }
        __syncthreads();
#pragma unroll
        for (int k = 0; k < 32; k++) {
            float4 a0 = *(const float4*)&sA[k][ty * 4];
            float4 a1 = *(const float4*)&sA[k][64 + ty * 4];
            ulonglong2 b0 = *(const ulonglong2*)&sB[k][tx * 4];
            float av[8] = { a0.x, a0.y, a0.z, a0.w, a1.x, a1.y, a1.z, a1.w };
            unsigned long long bp[2] = { b0.x, b0.y };
#pragma unroll
            for (int r = 0; r < 8; r++) {
                unsigned long long ad = dup2(av[r]);
                ffma2(accP[r][0], ad, bp[0]);
                ffma2(accP[r][1], ad, bp[1]);
            }
        }
    }

    float acc[8][4];
#pragma unroll
    for (int r = 0; r < 8; r++) {
        unpack2(accP[r][0], acc[r][0], acc[r][1]);
        unpack2(accP[r][1], acc[r][2], acc[r][3]);
    }

    int c0 = tx * 4;
    float bb[4];
#pragma unroll
    for (int j = 0; j < 4; j++) bb[j] = b2[c0 + j];
#pragma unroll
    for (int r = 0; r < 8; r++) {
        int row = (r < 4) ? (ty * 4 + r) : (64 + ty * 4 + (r - 4));
        size_t m = (size_t)(m0 + row);
        float4 o;
        o.x = fast_tanh(acc[r][0] + bb[0]);
        o.y = fast_tanh(acc[r][1] + bb[1]);
        o.z = fast_tanh(acc[r][2] + bb[2]);
        o.w = fast_tanh(acc[r][3] + bb[3]);
        *(float4*)(g_T2 + m * 128 + koff + c0) = o;
    }
}

// ---------------- R1: final_feature mean ----------------
__global__ void k_r1(float* __restrict__ out_ff) {
    int n = blockIdx.x, t = threadIdx.x;   // 64 threads
    float s = 0.f;
#pragma unroll 8
    for (int q = 0; q < SEQ_; q++) s += g_TA[((size_t)n * SEQ_ + q) * 64 + t];
    out_ff[n * 64 + t] = s * (1.0f / (float)SEQ_);
}

// ---------------- R2: pos/neg vec means + sq-norms ----------------
__global__ void k_r2() {
    __shared__ float ws[4];
    int n = blockIdx.x, t = threadIdx.x;   // 128 threads
    float s = 0.f;
#pragma unroll 8
    for (int q = 0; q < SEQ_; q++) s += g_T2[((size_t)n * SEQ_ + q) * 128 + t];
    float v = s * (1.0f / (float)SEQ_);
    if (t < 64) g_posvec[n * 64 + t] = v;
    else        g_negvec[n * 64 + (t - 64)] = v;
    float sq = v * v;
#pragma unroll
    for (int o = 16; o; o >>= 1) sq += __shfl_xor_sync(0xffffffffu, sq, o);
    if ((t & 31) == 0) ws[t >> 5] = sq;
    __syncthreads();
    if (t == 0) {
        g_psn[n] = ws[0] + ws[1];
        g_nsn[n] = ws[2] + ws[3];
    }
}

// ---------------- K8: similarity sums ----------------
#define SIM_SMEM ((3 * 128 * 65 + 3 * 128) * 4)
__global__ void k_sims() {
    extern __shared__ float s[];
    float* pI = s;
    float* pJ = pI + 128 * 65;
    float* nJ = pJ + 128 * 65;
    float* snI = nJ + 128 * 65;
    float* snP = snI + 128;
    float* snN = snP + 128;
    __shared__ float rp[256], rn[256];

    int bi = blockIdx.y, bj = blockIdx.x, t = threadIdx.x;
    for (int i = t; i < 128 * 64; i += 256) {
        int r = i >> 6, k = i & 63;
        pI[r * 65 + k] = g_posvec[(bi * 128 + r) * 64 + k];
        pJ[r * 65 + k] = g_posvec[(bj * 128 + r) * 64 + k];
        nJ[r * 65 + k] = g_negvec[(bj * 128 + r) * 64 + k];
    }
    if (t < 128) { snI[t] = g_psn[bi * 128 + t]; }
    else { snP[t - 128] = g_psn[bj * 128 + (t - 128)]; }
    if (t < 128) snN[t] = g_nsn[bj * 128 + t];
    __syncthreads();

    int tx = t & 15, ty = t >> 4;
    float lp = 0.f, ln = 0.f;
    {
        float acc[8][8];
#pragma unroll
        for (int r = 0; r < 8; r++)
#pragma unroll
            for (int c = 0; c < 8; c++) acc[r][c] = 0.f;
        for (int k = 0; k < 64; k++) {
            float a[8], b[8];
#pragma unroll
            for (int r = 0; r < 8; r++) a[r] = pI[(ty + 16 * r) * 65 + k];
#pragma unroll
            for (int c = 0; c < 8; c++) b[c] = pJ[(tx + 16 * c) * 65 + k];
#pragma unroll
            for (int r = 0; r < 8; r++)
#pragma unroll
                for (int c = 0; c < 8; c++) acc[r][c] += a[r] * b[c];
        }
#pragma unroll
        for (int r = 0; r < 8; r++)
#pragma unroll
            for (int c = 0; c < 8; c++) {
                float sq = snI[ty + 16 * r] + snP[tx + 16 * c] - 2.0f * acc[r][c];
                sq = fmaxf(sq, 0.0f);
                float d = (sq > 0.0f) ? sqrtf(sq) : 0.0f;
                lp += __expf(-d);
            }
    }
    {
        float acc[8][8];
#pragma unroll
        for (int r = 0; r < 8; r++)
#pragma unroll
            for (int c = 0; c < 8; c++) acc[r][c] = 0.f;
        for (int k = 0; k < 64; k++) {
            float a[8], b[8];
#pragma unroll
            for (int r = 0; r < 8; r++) a[r] = pI[(ty + 16 * r) * 65 + k];
#pragma unroll
            for (int c = 0; c < 8; c++) b[c] = nJ[(tx + 16 * c) * 65 + k];
#pragma unroll
            for (int r = 0; r < 8; r++)
#pragma unroll
                for (int c = 0; c < 8; c++) acc[r][c] += a[r] * b[c];
        }
#pragma unroll
        for (int r = 0; r < 8; r++)
#pragma unroll
            for (int c = 0; c < 8; c++) {
                float sq = snI[ty + 16 * r] + snN[tx + 16 * c] - 2.0f * acc[r][c];
                sq = fmaxf(sq, 0.0f);
                float d = (sq > 0.0f) ? sqrtf(sq) : 0.0f;
                ln += __expf(-d);
            }
    }
    rp[t] = lp; rn[t] = ln;
    __syncthreads();
    for (int o = 128; o; o >>= 1) {
        if (t < o) { rp[t] += rp[t + o]; rn[t] += rn[t + o]; }
        __syncthreads();
    }
    if (t == 0) {
        int bid = bi * 32 + bj;
        g_sp[bid] = rp[0]; g_sn[bid] = rn[0];
    }
}

__global__ void k_loss(float* __restrict__ out_loss) {
    __shared__ float rp[1024], rn[1024];
    int t = threadIdx.x;
    rp[t] = g_sp[t]; rn[t] = g_sn[t];
    __syncthreads();
    for (int o = 512; o; o >>= 1) {
        if (t < o) { rp[t] += rp[t + o]; rn[t] += rn[t + o]; }
        __syncthreads();
    }
    if (t == 0) out_loss[0] = -logf(rp[0] / rn[0]);
}

// ---------------- launch ----------------
extern "C" void kernel_launch(void* const* d_in, const int* in_sizes, int n_in,
                              void* d_out, int out_size) {
    const float* A     = (const float*)d_in[0];
    const int*   C     = (const int*)d_in[1];
    const float* L     = (const float*)d_in[2];
    const float* W1    = (const float*)d_in[3];
    const float* b1    = (const float*)d_in[4];
    const float* gam   = (const float*)d_in[5];
    const float* bet   = (const float*)d_in[6];
    const float* sig   = (const float*)d_in[7];
    const float* Pw    = (const float*)d_in[8];
    const float* Nw    = (const float*)d_in[9];
    const float* Wp1   = (const float*)d_in[10];
    const float* bp1   = (const float*)d_in[11];
    const float* Wp2   = (const float*)d_in[12];
    const float* bp2   = (const float*)d_in[13];
    const float* Wq1   = (const float*)d_in[14];
    const float* bq1   = (const float*)d_in[15];
    const float* Wq2   = (const float*)d_in[16];
    const float* bq2   = (const float*)d_in[17];
    const float* Wa    = (const float*)d_in[18];
    const float* ba    = (const float*)d_in[19];

    float* out = (float*)d_out;
    float* out_ff   = out;                    // [4096*64]
    float* out_loss = out + N_ * RED_;        // [1]
    float* out_D    = out + N_ * RED_ + 1;    // [4096*4096], only 4B-aligned!

    cudaFuncSetAttribute(k_sims, cudaFuncAttributeMaxDynamicSharedMemorySize, SIM_SMEM);

    k_gather_h<<<N_, 128>>>(A, C, W1, b1);
    k_bnstats<<<1, 1024>>>();
    k_emb<<<512, 256>>>(gam, bet);
    k_dstats<<<dim3(32, 32), 256>>>(sig);
    k_dconsts<<<1, 1024>>>();
    k_dfinal<<<(N_ * (N_ / 4)) / 256, 256>>>(out_D);
    k_gemm1<<<M1_ / 128, 384>>>(L, Pw, Nw, C, Wp1, bp1, Wq1, bq1, Wa, ba);
    k_gemm2<<<dim3(M1_ / 128, 2), 256>>>(Wp2, bp2, Wq2, bq2);
    k_r1<<<N_, 64>>>(out_ff);
    k_r2<<<N_, 128>>>();
    k_sims<<<dim3(32, 32), 256, SIM_SMEM>>>();
    k_loss<<<1, 1024>>>(out_loss);
}

// round 9
// speedup vs baseline: 4.0397x; 1.4206x over previous
#include <cuda_runtime.h>
#include <cuda_bf16.h>
#include <math.h>
#include <stdint.h>

#define N_   4096
#define SEQ_ 41
#define VEC_ 15
#define T_   8
#define EMB_ 32
#define LDIM_ 256
#define RED_ 64
#define M1_  (N_ * SEQ_)   // 167936 rows = 1312 tiles of 128

// ---------------- scratch (device globals; no allocation) ----------------
__device__ float g_h[N_ * EMB_];
__device__ float g_emb[N_ * EMB_];
__device__ float g_sqn[N_];
__device__ float g_mu[EMB_];
__device__ float g_rstd[EMB_];
__device__ float g_psum[1024];
__device__ float g_pmin[1024];
__device__ float g_pmax[1024];
__device__ float g_dc[3];
__device__ float g_posvec[N_ * RED_];
__device__ float g_negvec[N_ * RED_];
__device__ float g_psn[N_];
__device__ float g_nsn[N_];
__device__ float g_sp[1024];
__device__ float g_sn[1024];
__device__ float g_TA[(size_t)M1_ * 64];            // tanh((mp+mn)*z_a + ba)
__device__ float g_T2[(size_t)M1_ * 128];           // layer-2 tanh outputs
__device__ float g_Draw[(size_t)N_ * N_];           // raw exp vals
// bf16-split intermediates
__device__ __nv_bfloat16 g_Hh[(size_t)M1_ * 128];   // H hi
__device__ __nv_bfloat16 g_Hl[(size_t)M1_ * 128];   // H lo
__device__ __nv_bfloat16 g_W1Th[3 * 64 * 256];      // [w][n][k], w: p,q,a
__device__ __nv_bfloat16 g_W1Tl[3 * 64 * 256];
__device__ __nv_bfloat16 g_W2Th[2 * 64 * 64];       // [p][n][k]
__device__ __nv_bfloat16 g_W2Tl[2 * 64 * 64];

__device__ __forceinline__ float fast_tanh(float x) {
    float e = __expf(2.0f * x);
    return 1.0f - 2.0f / (e + 1.0f);
}
__device__ __forceinline__ void bf16split(float x, __nv_bfloat16& h, __nv_bfloat16& l) {
    h = __float2bfloat16(x);
    l = __float2bfloat16(x - __bfloat162float(h));
}
__device__ __forceinline__ unsigned packbf2(__nv_bfloat16 a, __nv_bfloat16 b) {
    __nv_bfloat162 t = __nv_bfloat162(a, b);
    return *reinterpret_cast<unsigned*>(&t);
}

// bf16 warp MMA: D(16x8,f32) += A(16x16,row) * B(16x8,col)
__device__ __forceinline__ void mma_bf16(float c[4], const uint32_t a[4],
                                         uint32_t b0, uint32_t b1) {
    asm volatile(
        "mma.sync.aligned.m16n8k16.row.col.f32.bf16.bf16.f32 "
        "{%0,%1,%2,%3}, {%4,%5,%6,%7}, {%8,%9}, {%0,%1,%2,%3};"
        : "+f"(c[0]), "+f"(c[1]), "+f"(c[2]), "+f"(c[3])
        : "r"(a[0]), "r"(a[1]), "r"(a[2]), "r"(a[3]), "r"(b0), "r"(b1));
}

// ---------------- K1: gather + interp + h = tanh(flat@W1 + b1) ----------------
__global__ void k_gather_h(const float* __restrict__ A, const int* __restrict__ C,
                           const float* __restrict__ W1, const float* __restrict__ b1) {
    __shared__ float flat[120];
    int n = blockIdx.x;
    int t = threadIdx.x;
    int start = C[2 * n], end = C[2 * n + 1];
    int len = end - start + 1;
    if (t < 120) {
        int j = t / VEC_, v = t % VEC_;
        float scale = (float)len / (float)T_;
        float src = fmaxf(scale * ((float)j + 0.5f) - 0.5f, 0.0f);
        int i0 = min((int)floorf(src), len - 1);
        int i1 = min(i0 + 1, len - 1);
        float w = src - (float)i0;
        const float* Ar = A + (size_t)n * SEQ_ * VEC_;
        float g0 = Ar[(start + i0) * VEC_ + v];
        float g1 = Ar[(start + i1) * VEC_ + v];
        flat[t] = (1.0f - w) * g0 + w * g1;
    }
    __syncthreads();
    if (t < 32) {
        float acc = b1[t];
#pragma unroll
        for (int k = 0; k < 120; k++) acc += flat[k] * W1[k * 32 + t];
        g_h[n * 32 + t] = tanhf(acc);
    }
}

// ---------------- K2: batchnorm stats ----------------
__global__ void k_bnstats() {
    __shared__ float ssum[32][33];
    __shared__ float ssq[32][33];
    int c = threadIdx.x & 31, g = threadIdx.x >> 5;
    float s = 0.f, q = 0.f;
    for (int n = g; n < N_; n += 32) {
        float v = g_h[n * 32 + c];
        s += v; q += v * v;
    }
    ssum[g][c] = s; ssq[g][c] = q;
    __syncthreads();
    if (threadIdx.x < 32) {
        float S = 0.f, Q = 0.f;
        for (int gg = 0; gg < 32; gg++) { S += ssum[gg][threadIdx.x]; Q += ssq[gg][threadIdx.x]; }
        float mu = S / (float)N_;
        float var = Q / (float)N_ - mu * mu;
        g_mu[threadIdx.x] = mu;
        g_rstd[threadIdx.x] = rsqrtf(var + 1e-5f);
    }
}

// ---------------- K3: emb + row sq-norms ----------------
__global__ void k_emb(const float* __restrict__ gamma, const float* __restrict__ beta) {
    int idx = blockIdx.x * 256 + threadIdx.x;
    int c = idx & 31;
    float e = gamma[c] * (g_h[idx] - g_mu[c]) * g_rstd[c] + beta[c];
    g_emb[idx] = e;
    float sq = e * e;
#pragma unroll
    for (int o = 16; o; o >>= 1) sq += __shfl_xor_sync(0xffffffffu, sq, o);
    if (c == 0) g_sqn[idx >> 5] = sq;
}

// ---------------- D tile GEMM helper ----------------
__device__ __forceinline__ void d_tile_gemm(int bi, int bj, int t,
                                            float sI[128][33], float sJ[128][33],
                                            float snI[128], float snJ[128],
                                            float acc[8][8]) {
    for (int i = t; i < 128 * 32; i += 256) {
        int r = i >> 5, k = i & 31;
        sI[r][k] = g_emb[(bi * 128 + r) * 32 + k];
        sJ[r][k] = g_emb[(bj * 128 + r) * 32 + k];
    }
    if (t < 128) snI[t] = g_sqn[bi * 128 + t];
    else snJ[t - 128] = g_sqn[bj * 128 + (t - 128)];
    __syncthreads();
    int tx = t & 15, ty = t >> 4;
#pragma unroll
    for (int k = 0; k < 32; k++) {
        float a[8], b[8];
#pragma unroll
        for (int r = 0; r < 8; r++) a[r] = sI[ty + 16 * r][k];
#pragma unroll
        for (int c = 0; c < 8; c++) b[c] = sJ[tx + 16 * c][k];
#pragma unroll
        for (int r = 0; r < 8; r++)
#pragma unroll
            for (int c = 0; c < 8; c++) acc[r][c] += a[r] * b[c];
    }
}

__global__ void k_dstats(const float* __restrict__ sigma_p) {
    __shared__ float sI[128][33], sJ[128][33];
    __shared__ float snI[128], snJ[128];
    __shared__ float rs[256], rmn[256], rmx[256];
    int bi = blockIdx.y, bj = blockIdx.x, t = threadIdx.x;
    float acc[8][8];
#pragma unroll
    for (int r = 0; r < 8; r++)
#pragma unroll
        for (int c = 0; c < 8; c++) acc[r][c] = 0.f;
    d_tile_gemm(bi, bj, t, sI, sJ, snI, snJ, acc);
    float inv2s;
    { float sg = sigma_p[0]; inv2s = 0.5f / (sg * sg); }
    int tx = t & 15, ty = t >> 4;
    float lsum = 0.f, lmin = 3.4e38f, lmax = -3.4e38f;
#pragma unroll
    for (int r = 0; r < 8; r++) {
        int gi = bi * 128 + ty + 16 * r;
#pragma unroll
        for (int c = 0; c < 8; c++) {
            int gj = bj * 128 + tx + 16 * c;
            float sq = snI[ty + 16 * r] + snJ[tx + 16 * c] - 2.0f * acc[r][c];
            sq = fmaxf(sq, 0.0f);
            float d = (sq > 0.0f) ? sqrtf(sq) : 0.0f;
            float val = __expf(-d * inv2s);
            g_Draw[(size_t)gi * N_ + gj] = val;
            if (gi != gj) { lsum += val; lmin = fminf(lmin, val); lmax = fmaxf(lmax, val); }
        }
    }
    rs[t] = lsum; rmn[t] = lmin; rmx[t] = lmax;
    __syncthreads();
    for (int o = 128; o; o >>= 1) {
        if (t < o) {
            rs[t] += rs[t + o];
            rmn[t] = fminf(rmn[t], rmn[t + o]);
            rmx[t] = fmaxf(rmx[t], rmx[t + o]);
        }
        __syncthreads();
    }
    if (t == 0) {
        int bid = bi * 32 + bj;
        g_psum[bid] = rs[0]; g_pmin[bid] = rmn[0]; g_pmax[bid] = rmx[0];
    }
}

__global__ void k_dconsts() {
    __shared__ float rs[1024], rmn[1024], rmx[1024];
    int t = threadIdx.x;
    rs[t] = g_psum[t]; rmn[t] = g_pmin[t]; rmx[t] = g_pmax[t];
    __syncthreads();
    for (int o = 512; o; o >>= 1) {
        if (t < o) {
            rs[t] += rs[t + o];
            rmn[t] = fminf(rmn[t], rmn[t + o]);
            rmx[t] = fmaxf(rmx[t], rmx[t + o]);
        }
        __syncthreads();
    }
    if (t == 0) {
        float avg = rs[0] / ((float)N_ * (float)(N_ - 1));
        float mn = (rmn[0] < avg) ? 0.0f : rmn[0];
        float mx = rmx[0];
        if (mx == mn) mx = mn + 1.0f;
        g_dc[0] = avg; g_dc[1] = mn; g_dc[2] = 1.0f / (mx - mn);
    }
}

// D finalize: output pointer only 4B-aligned -> scalar stores
__global__ void k_dfinal(float* __restrict__ D) {
    float avg = g_dc[0], mn = g_dc[1], inv = g_dc[2];
    size_t base = ((size_t)blockIdx.x * 256 + threadIdx.x) * 4;
    float4 v = *(const float4*)(g_Draw + base);
    float vv[4] = { v.x, v.y, v.z, v.w };
#pragma unroll
    for (int j = 0; j < 4; j++) {
        size_t idx = base + j;
        int gi = (int)(idx >> 12);
        int gj = (int)(idx & 4095);
        float dt = (vv[j] < avg) ? 0.0f : vv[j];
        D[idx] = (gi == gj) ? 1.0f : (dt - mn) * inv;
    }
}

// ---------------- W split/transpose precompute ----------------
__global__ void k_wsplit(const float* __restrict__ Wp1, const float* __restrict__ Wq1,
                         const float* __restrict__ Wa,
                         const float* __restrict__ Wp2, const float* __restrict__ Wq2) {
    int idx = blockIdx.x * 256 + threadIdx.x;
    if (idx < 3 * 64 * 256) {
        int w = idx >> 14;
        int n = (idx >> 8) & 63;
        int k = idx & 255;
        const float* W = (w == 0) ? Wp1 : (w == 1) ? Wq1 : Wa;
        float x = W[k * 64 + n];
        __nv_bfloat16 h, l; bf16split(x, h, l);
        g_W1Th[idx] = h; g_W1Tl[idx] = l;
    }
    if (idx < 2 * 64 * 64) {
        int p = idx >> 12;
        int n = (idx >> 6) & 63;
        int k = idx & 63;
        const float* W = p ? Wq2 : Wp2;
        float x = W[k * 64 + n];
        __nv_bfloat16 h, l; bf16split(x, h, l);
        g_W2Th[idx] = h; g_W2Tl[idx] = l;
    }
}

// ---------------- GEMM1 (mma.sync bf16): Z = L[128,256] @ [Wp1|Wq1|Wa] ----------------
// 512 thr = 16 warps; warp tile 32(M) x 48(N); K chunks of 64; 3 split passes.
// dyn smem: Ah[128*72] Al Bh[192*72] Bl (bf16, pad 72 -> conflict-free frags)
#define G1_A_ELEM (128 * 72)
#define G1_B_ELEM (192 * 72)
#define G1_SMEM ((2 * G1_A_ELEM + 2 * G1_B_ELEM) * 2)

__global__ void __launch_bounds__(512)
k_gemm1_mma(const float* __restrict__ L, const float* __restrict__ Pw,
            const float* __restrict__ Nw, const int* __restrict__ C,
            const float* __restrict__ bp1, const float* __restrict__ bq1,
            const float* __restrict__ ba) {
    extern __shared__ __nv_bfloat16 sm1[];
    __nv_bfloat16* sAh = sm1;
    __nv_bfloat16* sAl = sAh + G1_A_ELEM;
    __nv_bfloat16* sBh = sAl + G1_A_ELEM;
    __nv_bfloat16* sBl = sBh + G1_B_ELEM;
    __shared__ float sMp[128], sMn[128], sBias[192];

    int t = threadIdx.x;
    int m0 = blockIdx.x * 128;
    int wid = t >> 5, lane = t & 31;
    int wr = wid >> 2, wc = wid & 3;        // 4x4 warps
    int g = lane >> 2, t4 = lane & 3;

    if (t < 128) {
        int m = m0 + t;
        int n = m / SEQ_, s = m - n * SEQ_;
        int st = C[2 * n], en = C[2 * n + 1];
        bool in = (s >= st && s <= en);
        sMp[t] = in ? Pw[n * SEQ_ + s] : 0.0f;
        sMn[t] = in ? 0.0f : Nw[n * SEQ_ + s];
    } else if (t < 320) {
        int c = t - 128;
        sBias[c] = (c < 64) ? bp1[c] : (c < 128) ? bq1[c - 64] : ba[c - 128];
    }

    float acc[2][6][4];
#pragma unroll
    for (int r = 0; r < 2; r++)
#pragma unroll
        for (int c = 0; c < 6; c++)
#pragma unroll
            for (int j = 0; j < 4; j++) acc[r][c][j] = 0.f;

    for (int kc = 0; kc < 4; kc++) {
        __syncthreads();
        // stage A: 128 rows x 64 k (split fp32 -> hi/lo bf16)
        for (int i = t; i < 2048; i += 512) {
            int r = i >> 4, k4 = (i & 15) * 4;
            float4 v = *(const float4*)(L + (size_t)(m0 + r) * 256 + kc * 64 + k4);
            float xs[4] = { v.x, v.y, v.z, v.w };
            __nv_bfloat16 h[4], l[4];
#pragma unroll
            for (int j = 0; j < 4; j++) bf16split(xs[j], h[j], l[j]);
            uint2 uh = { packbf2(h[0], h[1]), packbf2(h[2], h[3]) };
            uint2 ul = { packbf2(l[0], l[1]), packbf2(l[2], l[3]) };
            *(uint2*)(sAh + r * 72 + k4) = uh;
            *(uint2*)(sAl + r * 72 + k4) = ul;
        }
        // stage B: 192 n x 64 k from pre-split transposed weights
        for (int i = t; i < 1536; i += 512) {
            int n = i >> 3, k8 = (i & 7) * 8;
            size_t goff = (size_t)(n >> 6) * 16384 + (size_t)(n & 63) * 256 + kc * 64 + k8;
            *(uint4*)(sBh + n * 72 + k8) = *(const uint4*)(g_W1Th + goff);
            *(uint4*)(sBl + n * 72 + k8) = *(const uint4*)(g_W1Tl + goff);
        }
        __syncthreads();

#pragma unroll
        for (int pass = 0; pass < 3; pass++) {
            const __nv_bfloat16* A = (pass == 2) ? sAl : sAh;
            const __nv_bfloat16* B = (pass == 1) ? sBl : sBh;
#pragma unroll
            for (int ks = 0; ks < 4; ks++) {
                int k0 = ks * 16;
                uint32_t af[2][4];
#pragma unroll
                for (int rt = 0; rt < 2; rt++) {
                    int row = wr * 32 + rt * 16;
                    af[rt][0] = *(const uint32_t*)(A + (row + g) * 72 + k0 + 2 * t4);
                    af[rt][1] = *(const uint32_t*)(A + (row + g + 8) * 72 + k0 + 2 * t4);
                    af[rt][2] = *(const uint32_t*)(A + (row + g) * 72 + k0 + 2 * t4 + 8);
                    af[rt][3] = *(const uint32_t*)(A + (row + g + 8) * 72 + k0 + 2 * t4 + 8);
                }
#pragma unroll
                for (int ct = 0; ct < 6; ct++) {
                    int n = wc * 48 + ct * 8;
                    uint32_t b0 = *(const uint32_t*)(B + (n + g) * 72 + k0 + 2 * t4);
                    uint32_t b1 = *(const uint32_t*)(B + (n + g) * 72 + k0 + 2 * t4 + 8);
                    mma_bf16(acc[0][ct], af[0], b0, b1);
                    mma_bf16(acc[1][ct], af[1], b0, b1);
                }
            }
        }
    }

    // epilogue: thread owns (r0,nn),(r0,nn+1),(r1,nn),(r1,nn+1) per (rt,ct)
#pragma unroll
    for (int rt = 0; rt < 2; rt++) {
        int r0 = wr * 32 + rt * 16 + g;
        int r1 = r0 + 8;
        size_t m0r0 = (size_t)(m0 + r0);
        size_t m0r1 = (size_t)(m0 + r1);
        float mp0 = sMp[r0], mn0 = sMn[r0];
        float mp1 = sMp[r1], mn1 = sMn[r1];
#pragma unroll
        for (int ct = 0; ct < 6; ct++) {
            int nn = wc * 48 + ct * 8 + 2 * t4;
            float b0 = sBias[nn], b1 = sBias[nn + 1];
            if (nn < 128) {
                float s0 = (nn < 64) ? mp0 : mn0;
                float s1 = (nn < 64) ? mp1 : mn1;
                float h00 = fast_tanh(s0 * acc[rt][ct][0] + b0);
                float h01 = fast_tanh(s0 * acc[rt][ct][1] + b1);
                float h10 = fast_tanh(s1 * acc[rt][ct][2] + b0);
                float h11 = fast_tanh(s1 * acc[rt][ct][3] + b1);
                __nv_bfloat16 hh, hl, h2h, h2l;
                bf16split(h00, hh, hl); bf16split(h01, h2h, h2l);
                *(unsigned*)(&g_Hh[m0r0 * 128 + nn]) = packbf2(hh, h2h);
                *(unsigned*)(&g_Hl[m0r0 * 128 + nn]) = packbf2(hl, h2l);
                bf16split(h10, hh, hl); bf16split(h11, h2h, h2l);
                *(unsigned*)(&g_Hh[m0r1 * 128 + nn]) = packbf2(hh, h2h);
                *(unsigned*)(&g_Hl[m0r1 * 128 + nn]) = packbf2(hl, h2l);
            } else {
                int na = nn - 128;
                float s0 = mp0 + mn0, s1 = mp1 + mn1;
                float2 o0, o1;
                o0.x = fast_tanh(s0 * acc[rt][ct][0] + b0);
                o0.y = fast_tanh(s0 * acc[rt][ct][1] + b1);
                o1.x = fast_tanh(s1 * acc[rt][ct][2] + b0);
                o1.y = fast_tanh(s1 * acc[rt][ct][3] + b1);
                *(float2*)(g_TA + m0r0 * 64 + na) = o0;
                *(float2*)(g_TA + m0r1 * 64 + na) = o1;
            }
        }
    }
}

// ---------------- GEMM2 (mma.sync bf16): T2 = tanh(H @ blockdiag(Wp2,Wq2) + b2) ----
// 512 thr = 16 warps; warp tile 32(M) x 32(N); region = n/64 selects k-range.
// dyn smem: Hh[128*136] Hl + W[2][64][72] x hl
#define G2_H_ELEM (128 * 136)
#define G2_W_ELEM (2 * 64 * 72)
#define G2_SMEM ((2 * G2_H_ELEM + 2 * G2_W_ELEM) * 2)

__global__ void __launch_bounds__(512)
k_gemm2_mma(const float* __restrict__ bp2, const float* __restrict__ bq2) {
    extern __shared__ __nv_bfloat16 sm2[];
    __nv_bfloat16* sHh = sm2;
    __nv_bfloat16* sHl = sHh + G2_H_ELEM;
    __nv_bfloat16* sWh = sHl + G2_H_ELEM;
    __nv_bfloat16* sWl = sWh + G2_W_ELEM;
    __shared__ float sBias[128];

    int t = threadIdx.x;
    int m0 = blockIdx.x * 128;
    int wid = t >> 5, lane = t & 31;
    int wr = wid >> 2, wc = wid & 3;
    int g = lane >> 2, t4 = lane & 3;
    int region = wc >> 1;          // cols 0-63 -> 0, 64-127 -> 1
    int kbase = region * 64;

    if (t < 128) sBias[t] = (t < 64) ? bp2[t] : bq2[t - 64];

    // stage H (128 x 128) hi/lo
    for (int i = t; i < 2048; i += 512) {
        int r = i >> 4, k8 = (i & 15) * 8;
        size_t goff = (size_t)(m0 + r) * 128 + k8;
        *(uint4*)(sHh + r * 136 + k8) = *(const uint4*)(g_Hh + goff);
        *(uint4*)(sHl + r * 136 + k8) = *(const uint4*)(g_Hl + goff);
    }
    // stage W2 [2][64][64]
    for (int i = t; i < 1024; i += 512) {
        int rg = i >> 9, n = (i >> 3) & 63, k8 = (i & 7) * 8;
        size_t goff = (size_t)rg * 4096 + (size_t)n * 64 + k8;
        *(uint4*)(sWh + (rg * 64 + n) * 72 + k8) = *(const uint4*)(g_W2Th + goff);
        *(uint4*)(sWl + (rg * 64 + n) * 72 + k8) = *(const uint4*)(g_W2Tl + goff);
    }
    __syncthreads();

    float acc[2][4][4];
#pragma unroll
    for (int r = 0; r < 2; r++)
#pragma unroll
        for (int c = 0; c < 4; c++)
#pragma unroll
            for (int j = 0; j < 4; j++) acc[r][c][j] = 0.f;

#pragma unroll
    for (int pass = 0; pass < 3; pass++) {
        const __nv_bfloat16* A = (pass == 2) ? sHl : sHh;
        const __nv_bfloat16* B = (pass == 1) ? sWl : sWh;
#pragma unroll
        for (int ks = 0; ks < 4; ks++) {
            int k0 = kbase + ks * 16;
            uint32_t af[2][4];
#pragma unroll
            for (int rt = 0; rt < 2; rt++) {
                int row = wr * 32 + rt * 16;
                af[rt][0] = *(const uint32_t*)(A + (row + g) * 136 + k0 + 2 * t4);
                af[rt][1] = *(const uint32_t*)(A + (row + g + 8) * 136 + k0 + 2 * t4);
                af[rt][2] = *(const uint32_t*)(A + (row + g) * 136 + k0 + 2 * t4 + 8);
                af[rt][3] = *(const uint32_t*)(A + (row + g + 8) * 136 + k0 + 2 * t4 + 8);
            }
#pragma unroll
            for (int ct = 0; ct < 4; ct++) {
                int nl = (wc & 1) * 32 + ct * 8;   // local n within region
                int kk = ks * 16;
                const __nv_bfloat16* Bp = B + (region * 64 + nl + g) * 72 + kk + 2 * t4;
                uint32_t b0 = *(const uint32_t*)(Bp);
                uint32_t b1 = *(const uint32_t*)(Bp + 8);
                mma_bf16(acc[0][ct], af[0], b0, b1);
                mma_bf16(acc[1][ct], af[1], b0, b1);
            }
        }
    }

#pragma unroll
    for (int rt = 0; rt < 2; rt++) {
        int r0 = wr * 32 + rt * 16 + g;
        int r1 = r0 + 8;
        size_t m0r0 = (size_t)(m0 + r0);
        size_t m0r1 = (size_t)(m0 + r1);
#pragma unroll
        for (int ct = 0; ct < 4; ct++) {
            int nn = wc * 32 + ct * 8 + 2 * t4;
            float b0 = sBias[nn], b1 = sBias[nn + 1];
            float2 o0, o1;
            o0.x = fast_tanh(acc[rt][ct][0] + b0);
            o0.y = fast_tanh(acc[rt][ct][1] + b1);
            o1.x = fast_tanh(acc[rt][ct][2] + b0);
            o1.y = fast_tanh(acc[rt][ct][3] + b1);
            *(float2*)(g_T2 + m0r0 * 128 + nn) = o0;
            *(float2*)(g_T2 + m0r1 * 128 + nn) = o1;
        }
    }
}

// ---------------- R1: final_feature mean ----------------
__global__ void k_r1(float* __restrict__ out_ff) {
    int n = blockIdx.x, t = threadIdx.x;   // 64 threads
    float s = 0.f;
#pragma unroll 8
    for (int q = 0; q < SEQ_; q++) s += g_TA[((size_t)n * SEQ_ + q) * 64 + t];
    out_ff[n * 64 + t] = s * (1.0f / (float)SEQ_);
}

// ---------------- R2: pos/neg vec means + sq-norms ----------------
__global__ void k_r2() {
    __shared__ float ws[4];
    int n = blockIdx.x, t = threadIdx.x;   // 128 threads
    float s = 0.f;
#pragma unroll 8
    for (int q = 0; q < SEQ_; q++) s += g_T2[((size_t)n * SEQ_ + q) * 128 + t];
    float v = s * (1.0f / (float)SEQ_);
    if (t < 64) g_posvec[n * 64 + t] = v;
    else        g_negvec[n * 64 + (t - 64)] = v;
    float sq = v * v;
#pragma unroll
    for (int o = 16; o; o >>= 1) sq += __shfl_xor_sync(0xffffffffu, sq, o);
    if ((t & 31) == 0) ws[t >> 5] = sq;
    __syncthreads();
    if (t == 0) {
        g_psn[n] = ws[0] + ws[1];
        g_nsn[n] = ws[2] + ws[3];
    }
}

// ---------------- K8: similarity sums ----------------
#define SIM_SMEM ((3 * 128 * 65 + 3 * 128) * 4)
__global__ void k_sims() {
    extern __shared__ float s[];
    float* pI = s;
    float* pJ = pI + 128 * 65;
    float* nJ = pJ + 128 * 65;
    float* snI = nJ + 128 * 65;
    float* snP = snI + 128;
    float* snN = snP + 128;
    __shared__ float rp[256], rn[256];

    int bi = blockIdx.y, bj = blockIdx.x, t = threadIdx.x;
    for (int i = t; i < 128 * 64; i += 256) {
        int r = i >> 6, k = i & 63;
        pI[r * 65 + k] = g_posvec[(bi * 128 + r) * 64 + k];
        pJ[r * 65 + k] = g_posvec[(bj * 128 + r) * 64 + k];
        nJ[r * 65 + k] = g_negvec[(bj * 128 + r) * 64 + k];
    }
    if (t < 128) { snI[t] = g_psn[bi * 128 + t]; }
    else { snP[t - 128] = g_psn[bj * 128 + (t - 128)]; }
    if (t < 128) snN[t] = g_nsn[bj * 128 + t];
    __syncthreads();

    int tx = t & 15, ty = t >> 4;
    float lp = 0.f, ln = 0.f;
    {
        float acc[8][8];
#pragma unroll
        for (int r = 0; r < 8; r++)
#pragma unroll
            for (int c = 0; c < 8; c++) acc[r][c] = 0.f;
        for (int k = 0; k < 64; k++) {
            float a[8], b[8];
#pragma unroll
            for (int r = 0; r < 8; r++) a[r] = pI[(ty + 16 * r) * 65 + k];
#pragma unroll
            for (int c = 0; c < 8; c++) b[c] = pJ[(tx + 16 * c) * 65 + k];
#pragma unroll
            for (int r = 0; r < 8; r++)
#pragma unroll
                for (int c = 0; c < 8; c++) acc[r][c] += a[r] * b[c];
        }
#pragma unroll
        for (int r = 0; r < 8; r++)
#pragma unroll
            for (int c = 0; c < 8; c++) {
                float sq = snI[ty + 16 * r] + snP[tx + 16 * c] - 2.0f * acc[r][c];
                sq = fmaxf(sq, 0.0f);
                float d = (sq > 0.0f) ? sqrtf(sq) : 0.0f;
                lp += __expf(-d);
            }
    }
    {
        float acc[8][8];
#pragma unroll
        for (int r = 0; r < 8; r++)
#pragma unroll
            for (int c = 0; c < 8; c++) acc[r][c] = 0.f;
        for (int k = 0; k < 64; k++) {
            float a[8], b[8];
#pragma unroll
            for (int r = 0; r < 8; r++) a[r] = pI[(ty + 16 * r) * 65 + k];
#pragma unroll
            for (int c = 0; c < 8; c++) b[c] = nJ[(tx + 16 * c) * 65 + k];
#pragma unroll
            for (int r = 0; r < 8; r++)
#pragma unroll
                for (int c = 0; c < 8; c++) acc[r][c] += a[r] * b[c];
        }
#pragma unroll
        for (int r = 0; r < 8; r++)
#pragma unroll
            for (int c = 0; c < 8; c++) {
                float sq = snI[ty + 16 * r] + snN[tx + 16 * c] - 2.0f * acc[r][c];
                sq = fmaxf(sq, 0.0f);
                float d = (sq > 0.0f) ? sqrtf(sq) : 0.0f;
                ln += __expf(-d);
            }
    }
    rp[t] = lp; rn[t] = ln;
    __syncthreads();
    for (int o = 128; o; o >>= 1) {
        if (t < o) { rp[t] += rp[t + o]; rn[t] += rn[t + o]; }
        __syncthreads();
    }
    if (t == 0) {
        int bid = bi * 32 + bj;
        g_sp[bid] = rp[0]; g_sn[bid] = rn[0];
    }
}

__global__ void k_loss(float* __restrict__ out_loss) {
    __shared__ float rp[1024], rn[1024];
    int t = threadIdx.x;
    rp[t] = g_sp[t]; rn[t] = g_sn[t];
    __syncthreads();
    for (int o = 512; o; o >>= 1) {
        if (t < o) { rp[t] += rp[t + o]; rn[t] += rn[t + o]; }
        __syncthreads();
    }
    if (t == 0) out_loss[0] = -logf(rp[0] / rn[0]);
}

// ---------------- launch ----------------
extern "C" void kernel_launch(void* const* d_in, const int* in_sizes, int n_in,
                              void* d_out, int out_size) {
    const float* A     = (const float*)d_in[0];
    const int*   C     = (const int*)d_in[1];
    const float* L     = (const float*)d_in[2];
    const float* W1    = (const float*)d_in[3];
    const float* b1    = (const float*)d_in[4];
    const float* gam   = (const float*)d_in[5];
    const float* bet   = (const float*)d_in[6];
    const float* sig   = (const float*)d_in[7];
    const float* Pw    = (const float*)d_in[8];
    const float* Nw    = (const float*)d_in[9];
    const float* Wp1   = (const float*)d_in[10];
    const float* bp1   = (const float*)d_in[11];
    const float* Wp2   = (const float*)d_in[12];
    const float* bp2   = (const float*)d_in[13];
    const float* Wq1   = (const float*)d_in[14];
    const float* bq1   = (const float*)d_in[15];
    const float* Wq2   = (const float*)d_in[16];
    const float* bq2   = (const float*)d_in[17];
    const float* Wa    = (const float*)d_in[18];
    const float* ba    = (const float*)d_in[19];

    float* out = (float*)d_out;
    float* out_ff   = out;                    // [4096*64]
    float* out_loss = out + N_ * RED_;        // [1]
    float* out_D    = out + N_ * RED_ + 1;    // [4096*4096], only 4B-aligned!

    cudaFuncSetAttribute(k_sims, cudaFuncAttributeMaxDynamicSharedMemorySize, SIM_SMEM);
    cudaFuncSetAttribute(k_gemm1_mma, cudaFuncAttributeMaxDynamicSharedMemorySize, G1_SMEM);
    cudaFuncSetAttribute(k_gemm2_mma, cudaFuncAttributeMaxDynamicSharedMemorySize, G2_SMEM);

    k_wsplit<<<192, 256>>>(Wp1, Wq1, Wa, Wp2, Wq2);
    k_gather_h<<<N_, 128>>>(A, C, W1, b1);
    k_bnstats<<<1, 1024>>>();
    k_emb<<<512, 256>>>(gam, bet);
    k_dstats<<<dim3(32, 32), 256>>>(sig);
    k_dconsts<<<1, 1024>>>();
    k_dfinal<<<(N_ * (N_ / 4)) / 256, 256>>>(out_D);
    k_gemm1_mma<<<M1_ / 128, 512, G1_SMEM>>>(L, Pw, Nw, C, bp1, bq1, ba);
    k_gemm2_mma<<<M1_ / 128, 512, G2_SMEM>>>(bp2, bq2);
    k_r1<<<N_, 64>>>(out_ff);
    k_r2<<<N_, 128>>>();
    k_sims<<<dim3(32, 32), 256, SIM_SMEM>>>();
    k_loss<<<1, 1024>>>(out_loss);
}